// round 12
// baseline (speedup 1.0000x reference)
#include <cuda_runtime.h>
#include <cuda_bf16.h>
#include <math.h>
#include <cstdint>

#define NMAX 100000
#define EMAX 1000000
#define HID 128

// ---------------- scratch (device globals; no runtime allocation) ------------
__device__ __align__(16) int   g_cnt[NMAX];
__device__ __align__(16) int   g_off[NMAX + 1];
__device__ __align__(16) int   g_cur[NMAX];
__device__ __align__(16) float g_dinv[NMAX];
__device__ __align__(16) int2  g_edge[EMAX];   // {src, w bits} interleaved
__device__ __align__(16) float g_buf1[(size_t)NMAX * HID];
__device__ __align__(16) float g_buf2[(size_t)NMAX * HID];
__device__ __align__(16) int   g_bsums[64];
__device__ int g_is64;

static inline int ceil_div(int a, int b) { return (a + b - 1) / b; }

// ---------------- helpers ----------------------------------------------------
__device__ __forceinline__ int load_idx(const void* p, int is64, long long i) {
    if (is64) return (int)((const long long*)p)[i];
    return ((const int*)p)[i];
}

__device__ __forceinline__ void split2(float2 v, uint32_t& hi, uint32_t& lo) {
    __nv_bfloat16 hx = __float2bfloat16(v.x), hy = __float2bfloat16(v.y);
    float rx = v.x - __bfloat162float(hx);
    float ry = v.y - __bfloat162float(hy);
    __nv_bfloat16 lx = __float2bfloat16(rx), ly = __float2bfloat16(ry);
    hi = ((uint32_t)__bfloat16_as_ushort(hy) << 16) | (uint32_t)__bfloat16_as_ushort(hx);
    lo = ((uint32_t)__bfloat16_as_ushort(ly) << 16) | (uint32_t)__bfloat16_as_ushort(lx);
}

__device__ __forceinline__ void mma_bf16(float& c0, float& c1, float& c2, float& c3,
                                         uint32_t a0, uint32_t a1, uint32_t a2, uint32_t a3,
                                         uint32_t b0, uint32_t b1) {
    asm volatile(
        "mma.sync.aligned.m16n8k16.row.col.f32.bf16.bf16.f32 "
        "{%0,%1,%2,%3}, {%4,%5,%6,%7}, {%8,%9}, {%0,%1,%2,%3};"
        : "+f"(c0), "+f"(c1), "+f"(c2), "+f"(c3)
        : "r"(a0), "r"(a1), "r"(a2), "r"(a3), "r"(b0), "r"(b1));
}

// ---------------- zero counters + dtype detect (fused) ------------------------
__global__ void k_zero_detect(const int* __restrict__ p, int nwords, int n) {
    int i = blockIdx.x * blockDim.x + threadIdx.x;
    if (i < n) g_cnt[i] = 0;
    if (blockIdx.x == 0 && threadIdx.x < 32) {
        bool oddzero = true;
        for (int j = threadIdx.x; j < 1024; j += 32) {
            int w = 2 * j + 1;
            if (w < nwords && p[w] != 0) oddzero = false;
        }
        oddzero = __all_sync(0xffffffffu, oddzero);
        if (threadIdx.x == 0) g_is64 = oddzero ? 1 : 0;
    }
}

__global__ void k_hist(const void* __restrict__ ei, int ne, int n) {
    int e = blockIdx.x * blockDim.x + threadIdx.x;
    int is64 = g_is64;
    if (e < ne) {
        int d = load_idx(ei, is64, (long long)ne + e);
        if (d >= 0 && d < n) atomicAdd(&g_cnt[d], 1);
    }
}

__global__ void k_scan1(int n) {
    __shared__ int sh[256];
    int tid  = threadIdx.x;
    int base = blockIdx.x * 2048;
    int vals[8];
    int tsum = 0;
#pragma unroll
    for (int v = 0; v < 8; v++) {
        int idx = base + tid * 8 + v;
        vals[v] = (idx < n) ? g_cnt[idx] : 0;
        tsum += vals[v];
    }
    sh[tid] = tsum;
    __syncthreads();
    for (int s = 1; s < 256; s <<= 1) {
        int t = (tid >= s) ? sh[tid - s] : 0;
        __syncthreads();
        sh[tid] += t;
        __syncthreads();
    }
    int run = sh[tid] - tsum;
    if (tid == 255) g_bsums[blockIdx.x] = sh[255];
#pragma unroll
    for (int v = 0; v < 8; v++) {
        int idx = base + tid * 8 + v;
        if (idx < n) g_off[idx] = run;
        run += vals[v];
    }
}

// scan3 with inline cross-block prefix (each 256-thr block lies in ONE 2048-group)
__global__ void k_scan3(int n, int ne) {
    __shared__ int pre;
    int b = blockIdx.x;
    int grp = b >> 3;  // (b*256)>>11
    if (threadIdx.x == 0) {
        int s = 0;
        for (int j = 0; j < grp; j++) s += g_bsums[j];
        pre = s;
    }
    __syncthreads();
    int i = b * 256 + threadIdx.x;
    if (i < n) {
        int o = g_off[i] + pre;
        g_off[i] = o;
        g_cur[i] = o;
        g_dinv[i] = rsqrtf((float)(g_cnt[i] + 1));  // +1 self loop
        if (i == 0) g_off[n] = ne;
    }
}

__global__ void k_fill(const void* __restrict__ ei, int ne, int n) {
    int e = blockIdx.x * blockDim.x + threadIdx.x;
    int is64 = g_is64;
    if (e < ne) {
        int s = load_idx(ei, is64, e);
        int d = load_idx(ei, is64, (long long)ne + e);
        if (s >= 0 && s < n && d >= 0 && d < n) {
            int p = atomicAdd(&g_cur[d], 1);
            g_edge[p] = make_int2(s, __float_as_int(g_dinv[s] * g_dinv[d]));
        }
    }
}

// ------- aggregation: Out[i] = sum norm_ij * X[j] + dinv_i^2 X[i] ------------
// warp per node; interleaved edge meta; 2-way unrolled for MLP
template <int F, int SRC, int DST>
__global__ void k_agg(const float* __restrict__ Xext, int n) {
    const float* X = (SRC == 0) ? Xext : (SRC == 1 ? g_buf1 : g_buf2);
    float* O       = (DST == 1) ? g_buf1 : g_buf2;
    int lane = threadIdx.x & 31, warp = threadIdx.x >> 5;
    int i = blockIdx.x * 8 + warp;
    if (i >= n) return;
    int e0 = g_off[i], e1 = g_off[i + 1];
    float di = g_dinv[i];
    float sw = di * di;

    if (F == 64) {
        float2 a0 = make_float2(0.f, 0.f), a1 = make_float2(0.f, 0.f);
        int e = e0;
        for (; e + 1 < e1; e += 2) {
            int2 ea = g_edge[e], eb = g_edge[e + 1];
            float wa = __int_as_float(ea.y), wb = __int_as_float(eb.y);
            float2 ha = ((const float2*)(X + (size_t)ea.x * 64))[lane];
            float2 hb = ((const float2*)(X + (size_t)eb.x * 64))[lane];
            a0.x = fmaf(wa, ha.x, a0.x); a0.y = fmaf(wa, ha.y, a0.y);
            a1.x = fmaf(wb, hb.x, a1.x); a1.y = fmaf(wb, hb.y, a1.y);
        }
        if (e < e1) {
            int2 ea = g_edge[e];
            float wa = __int_as_float(ea.y);
            float2 ha = ((const float2*)(X + (size_t)ea.x * 64))[lane];
            a0.x = fmaf(wa, ha.x, a0.x); a0.y = fmaf(wa, ha.y, a0.y);
        }
        float2 hs = ((const float2*)(X + (size_t)i * 64))[lane];
        float2 o;
        o.x = fmaf(sw, hs.x, a0.x + a1.x);
        o.y = fmaf(sw, hs.y, a0.y + a1.y);
        ((float2*)(O + (size_t)i * 64))[lane] = o;
    } else {
        float4 a0 = make_float4(0.f, 0.f, 0.f, 0.f), a1 = a0;
        int e = e0;
        for (; e + 1 < e1; e += 2) {
            int2 ea = g_edge[e], eb = g_edge[e + 1];
            float wa = __int_as_float(ea.y), wb = __int_as_float(eb.y);
            float4 ha = ((const float4*)(X + (size_t)ea.x * 128))[lane];
            float4 hb = ((const float4*)(X + (size_t)eb.x * 128))[lane];
            a0.x = fmaf(wa, ha.x, a0.x); a0.y = fmaf(wa, ha.y, a0.y);
            a0.z = fmaf(wa, ha.z, a0.z); a0.w = fmaf(wa, ha.w, a0.w);
            a1.x = fmaf(wb, hb.x, a1.x); a1.y = fmaf(wb, hb.y, a1.y);
            a1.z = fmaf(wb, hb.z, a1.z); a1.w = fmaf(wb, hb.w, a1.w);
        }
        if (e < e1) {
            int2 ea = g_edge[e];
            float wa = __int_as_float(ea.y);
            float4 ha = ((const float4*)(X + (size_t)ea.x * 128))[lane];
            a0.x = fmaf(wa, ha.x, a0.x); a0.y = fmaf(wa, ha.y, a0.y);
            a0.z = fmaf(wa, ha.z, a0.z); a0.w = fmaf(wa, ha.w, a0.w);
        }
        float4 hs = ((const float4*)(X + (size_t)i * 128))[lane];
        float4 o;
        o.x = fmaf(sw, hs.x, a0.x + a1.x);
        o.y = fmaf(sw, hs.y, a0.y + a1.y);
        o.z = fmaf(sw, hs.z, a0.z + a1.z);
        o.w = fmaf(sw, hs.w, a0.w + a1.w);
        ((float4*)(O + (size_t)i * 128))[lane] = o;
    }
}

// ------- bf16 split GEMM + bias + relu (layer 1): O[n,128] = relu(X@W + b) ---
// CTA: 128x128; 8 warps = 4(m) x 2(n); warp tile 32x64. 3 MMAs/frag pair.
template <int K, int SRC, int DST>
__global__ void __launch_bounds__(256)
k_gemm_mma(const float* __restrict__ W, const float* __restrict__ bias, int n) {
    __shared__ uint32_t XsHi[128 * 17], XsLo[128 * 17];
    __shared__ uint32_t WsHi[128 * 17], WsLo[128 * 17];

    const float* X = (SRC == 1) ? g_buf1 : g_buf2;
    float* O       = (DST == 1) ? g_buf1 : g_buf2;

    int tid = threadIdx.x, lane = tid & 31, warp = tid >> 5;
    int g = lane >> 2, t = lane & 3;
    int warp_m = warp & 3, warp_n = warp >> 2;
    int rb = blockIdx.x * 128;

    float c[2][8][4];
#pragma unroll
    for (int mi = 0; mi < 2; mi++)
#pragma unroll
        for (int nb = 0; nb < 8; nb++)
#pragma unroll
            for (int q = 0; q < 4; q++) c[mi][nb][q] = 0.f;

    const int NCH = K / 32;
    for (int ch = 0; ch < NCH; ch++) {
        int c0 = ch * 32;
        __syncthreads();
        for (int idx = tid; idx < 128 * 16; idx += 256) {
            int r = idx >> 4, kk = idx & 15;
            int row = rb + r;
            float2 v = (row < n) ? *(const float2*)(X + (size_t)row * K + c0 + 2 * kk)
                                 : make_float2(0.f, 0.f);
            uint32_t hi, lo;
            split2(v, hi, lo);
            XsHi[r * 17 + kk] = hi;
            XsLo[r * 17 + kk] = lo;
        }
        for (int idx = tid; idx < 128 * 16; idx += 256) {
            int kk = idx >> 7, nn = idx & 127;
            float2 v;
            v.x = W[(size_t)(c0 + 2 * kk) * 128 + nn];
            v.y = W[(size_t)(c0 + 2 * kk + 1) * 128 + nn];
            uint32_t hi, lo;
            split2(v, hi, lo);
            WsHi[nn * 17 + kk] = hi;
            WsLo[nn * 17 + kk] = lo;
        }
        __syncthreads();

#pragma unroll
        for (int step = 0; step < 2; step++) {
            int kb = step * 8;
            uint32_t bh0[8], bh1[8], bl0[8], bl1[8];
#pragma unroll
            for (int nb = 0; nb < 8; nb++) {
                int nl = warp_n * 64 + nb * 8 + g;
                bh0[nb] = WsHi[nl * 17 + kb + t];
                bh1[nb] = WsHi[nl * 17 + kb + t + 4];
                bl0[nb] = WsLo[nl * 17 + kb + t];
                bl1[nb] = WsLo[nl * 17 + kb + t + 4];
            }
#pragma unroll
            for (int mi = 0; mi < 2; mi++) {
                int rl = warp_m * 32 + mi * 16 + g;
                uint32_t ah0 = XsHi[rl * 17 + kb + t];
                uint32_t ah1 = XsHi[(rl + 8) * 17 + kb + t];
                uint32_t ah2 = XsHi[rl * 17 + kb + t + 4];
                uint32_t ah3 = XsHi[(rl + 8) * 17 + kb + t + 4];
                uint32_t al0 = XsLo[rl * 17 + kb + t];
                uint32_t al1 = XsLo[(rl + 8) * 17 + kb + t];
                uint32_t al2 = XsLo[rl * 17 + kb + t + 4];
                uint32_t al3 = XsLo[(rl + 8) * 17 + kb + t + 4];
#pragma unroll
                for (int nb = 0; nb < 8; nb++) {
                    mma_bf16(c[mi][nb][0], c[mi][nb][1], c[mi][nb][2], c[mi][nb][3],
                             ah0, ah1, ah2, ah3, bh0[nb], bh1[nb]);
                    mma_bf16(c[mi][nb][0], c[mi][nb][1], c[mi][nb][2], c[mi][nb][3],
                             ah0, ah1, ah2, ah3, bl0[nb], bl1[nb]);
                    mma_bf16(c[mi][nb][0], c[mi][nb][1], c[mi][nb][2], c[mi][nb][3],
                             al0, al1, al2, al3, bh0[nb], bh1[nb]);
                }
            }
        }
    }

#pragma unroll
    for (int mi = 0; mi < 2; mi++) {
        int row0 = rb + warp_m * 32 + mi * 16 + g;
        int row1 = row0 + 8;
#pragma unroll
        for (int nb = 0; nb < 8; nb++) {
            int col = warp_n * 64 + nb * 8 + 2 * t;
            float b0 = bias[col], b1 = bias[col + 1];
            if (row0 < n) {
                *(float2*)(O + (size_t)row0 * 128 + col) =
                    make_float2(fmaxf(c[mi][nb][0] + b0, 0.f), fmaxf(c[mi][nb][1] + b1, 0.f));
            }
            if (row1 < n) {
                *(float2*)(O + (size_t)row1 * 128 + col) =
                    make_float2(fmaxf(c[mi][nb][2] + b0, 0.f), fmaxf(c[mi][nb][3] + b1, 0.f));
            }
        }
    }
}

// ------- layer2 GEMM + bias + relu + head + log_softmax (fused) --------------
// CTA: 64 rows x 128 cols; 8 warps = 2(m) x 4(n); warp tile 32x32.
// H2 tile kept in smem (aliased over staging); head computed in-CTA; only `out`
// is written. Static smem layout:
//   [0,4352)      XsHi   (64x17 u32)      \
//   [4352,8704)   XsLo                     | aliased by H2 [0,32768)
//   [8704,17408)  WsHi   (128x17 u32)      |
//   [17408,26112) WsLo                    /
//   [32768,37888) Wt (10x128 f32, transposed)
//   [37888,37928) bls
__global__ void __launch_bounds__(256)
k_gemm2_head(const float* __restrict__ W, const float* __restrict__ bias,
             const float* __restrict__ Wl, const float* __restrict__ bl,
             float* __restrict__ out, int n) {
    __shared__ __align__(16) char sm[37952];
    uint32_t* XsHi = (uint32_t*)(sm);
    uint32_t* XsLo = (uint32_t*)(sm + 4352);
    uint32_t* WsHi = (uint32_t*)(sm + 8704);
    uint32_t* WsLo = (uint32_t*)(sm + 17408);
    float*    H2   = (float*)(sm);            // aliases staging, used after mainloop
    float*    Wt   = (float*)(sm + 32768);
    float*    bls  = (float*)(sm + 37888);

    const float* X = g_buf1;
    const int K = 128;

    int tid = threadIdx.x, lane = tid & 31, warp = tid >> 5;
    int g = lane >> 2, t = lane & 3;
    int warp_m = warp & 1, warp_n = warp >> 1;
    int rb = blockIdx.x * 64;

    // stage head weights (non-aliased region) once
    for (int idx = tid; idx < 1280; idx += 256) {
        int k = idx / 10, j = idx - 10 * k;
        Wt[j * 128 + k] = Wl[idx];
    }
    if (tid < 10) bls[tid] = bl[tid];

    float c[2][4][4];
#pragma unroll
    for (int mi = 0; mi < 2; mi++)
#pragma unroll
        for (int nb = 0; nb < 4; nb++)
#pragma unroll
            for (int q = 0; q < 4; q++) c[mi][nb][q] = 0.f;

    for (int ch = 0; ch < 4; ch++) {
        int c0 = ch * 32;
        __syncthreads();
        for (int idx = tid; idx < 64 * 16; idx += 256) {
            int r = idx >> 4, kk = idx & 15;
            int row = rb + r;
            float2 v = (row < n) ? *(const float2*)(X + (size_t)row * K + c0 + 2 * kk)
                                 : make_float2(0.f, 0.f);
            uint32_t hi, lo;
            split2(v, hi, lo);
            XsHi[r * 17 + kk] = hi;
            XsLo[r * 17 + kk] = lo;
        }
        for (int idx = tid; idx < 128 * 16; idx += 256) {
            int kk = idx >> 7, nn = idx & 127;
            float2 v;
            v.x = W[(size_t)(c0 + 2 * kk) * 128 + nn];
            v.y = W[(size_t)(c0 + 2 * kk + 1) * 128 + nn];
            uint32_t hi, lo;
            split2(v, hi, lo);
            WsHi[nn * 17 + kk] = hi;
            WsLo[nn * 17 + kk] = lo;
        }
        __syncthreads();

#pragma unroll
        for (int step = 0; step < 2; step++) {
            int kb = step * 8;
            uint32_t bh0[4], bh1[4], bl0[4], bl1[4];
#pragma unroll
            for (int nb = 0; nb < 4; nb++) {
                int nl = warp_n * 32 + nb * 8 + g;
                bh0[nb] = WsHi[nl * 17 + kb + t];
                bh1[nb] = WsHi[nl * 17 + kb + t + 4];
                bl0[nb] = WsLo[nl * 17 + kb + t];
                bl1[nb] = WsLo[nl * 17 + kb + t + 4];
            }
#pragma unroll
            for (int mi = 0; mi < 2; mi++) {
                int rl = warp_m * 32 + mi * 16 + g;
                uint32_t ah0 = XsHi[rl * 17 + kb + t];
                uint32_t ah1 = XsHi[(rl + 8) * 17 + kb + t];
                uint32_t ah2 = XsHi[rl * 17 + kb + t + 4];
                uint32_t ah3 = XsHi[(rl + 8) * 17 + kb + t + 4];
                uint32_t al0 = XsLo[rl * 17 + kb + t];
                uint32_t al1 = XsLo[(rl + 8) * 17 + kb + t];
                uint32_t al2 = XsLo[rl * 17 + kb + t + 4];
                uint32_t al3 = XsLo[(rl + 8) * 17 + kb + t + 4];
#pragma unroll
                for (int nb = 0; nb < 4; nb++) {
                    mma_bf16(c[mi][nb][0], c[mi][nb][1], c[mi][nb][2], c[mi][nb][3],
                             ah0, ah1, ah2, ah3, bh0[nb], bh1[nb]);
                    mma_bf16(c[mi][nb][0], c[mi][nb][1], c[mi][nb][2], c[mi][nb][3],
                             ah0, ah1, ah2, ah3, bl0[nb], bl1[nb]);
                    mma_bf16(c[mi][nb][0], c[mi][nb][1], c[mi][nb][2], c[mi][nb][3],
                             al0, al1, al2, al3, bh0[nb], bh1[nb]);
                }
            }
        }
    }

    // epilogue: bias + relu into smem H2 (overwrites staging; all MMA reads done)
    __syncthreads();
#pragma unroll
    for (int mi = 0; mi < 2; mi++) {
        int r0 = warp_m * 32 + mi * 16 + g;
        int r1 = r0 + 8;
#pragma unroll
        for (int nb = 0; nb < 4; nb++) {
            int col = warp_n * 32 + nb * 8 + 2 * t;
            float b0 = bias[col], b1 = bias[col + 1];
            H2[r0 * 128 + col]     = fmaxf(c[mi][nb][0] + b0, 0.f);
            H2[r0 * 128 + col + 1] = fmaxf(c[mi][nb][1] + b1, 0.f);
            H2[r1 * 128 + col]     = fmaxf(c[mi][nb][2] + b0, 0.f);
            H2[r1 * 128 + col + 1] = fmaxf(c[mi][nb][3] + b1, 0.f);
        }
    }
    __syncthreads();

    // head: warp handles 8 rows; log_softmax; write out only
    for (int it = 0; it < 8; it++) {
        int r = warp * 8 + it;
        int i = rb + r;
        if (i >= n) break;
        float4 hv = ((const float4*)(H2 + r * 128))[lane];
        float lg[10];
#pragma unroll
        for (int j = 0; j < 10; j++) {
            float4 wv = ((const float4*)(Wt + j * 128))[lane];
            float p = hv.x * wv.x + hv.y * wv.y + hv.z * wv.z + hv.w * wv.w;
#pragma unroll
            for (int o = 16; o; o >>= 1) p += __shfl_xor_sync(0xffffffffu, p, o);
            lg[j] = p + bls[j];
        }
        float m = lg[0];
#pragma unroll
        for (int j = 1; j < 10; j++) m = fmaxf(m, lg[j]);
        float s = 0.f;
#pragma unroll
        for (int j = 0; j < 10; j++) s += expf(lg[j] - m);
        float lse = m + logf(s);
        if (lane < 10) out[(size_t)i * 10 + lane] = lg[lane] - lse;
    }
}

// ---------------- launch -----------------------------------------------------
extern "C" void kernel_launch(void* const* d_in, const int* in_sizes, int n_in,
                              void* d_out, int out_size) {
    const float* x  = (const float*)d_in[0];
    const void*  ei = d_in[1];
    const float* W1 = (const float*)d_in[2];
    const float* b1 = (const float*)d_in[3];
    const float* W2 = (const float*)d_in[4];
    const float* b2 = (const float*)d_in[5];
    const float* Wl = (const float*)d_in[6];
    const float* bl = (const float*)d_in[7];
    float* out = (float*)d_out;

    int N = in_sizes[0] / 64;
    int E = in_sizes[1] / 2;

    // --- CSR build (zero+detect fused; scan2 folded into scan3) ---
    k_zero_detect<<<ceil_div(N, 256), 256>>>((const int*)ei, 2 * E >= 2048 ? 2048 : 2 * E, N);
    k_hist<<<ceil_div(E, 256), 256>>>(ei, E, N);
    k_scan1<<<ceil_div(N, 2048), 256>>>(N);
    k_scan3<<<ceil_div(N, 256), 256>>>(N, E);
    k_fill<<<ceil_div(E, 256), 256>>>(ei, E, N);

    // --- layer 1 (agg-first): agg x (64) -> buf1; mma gemm -> buf2
    k_agg<64, 0, 1><<<ceil_div(N, 8), 256>>>(x, N);
    k_gemm_mma<64, 1, 2><<<ceil_div(N, 128), 256>>>(W1, b1, N);

    // --- layer 2: agg buf2 (128) -> buf1; fused gemm+head -> out
    k_agg<128, 2, 1><<<ceil_div(N, 8), 256>>>(nullptr, N);
    k_gemm2_head<<<ceil_div(N, 64), 256>>>(W2, b2, Wl, bl, out, N);
}

// round 13
// speedup vs baseline: 1.0240x; 1.0240x over previous
#include <cuda_runtime.h>
#include <cuda_bf16.h>
#include <math.h>
#include <cstdint>

#define NMAX 100000
#define EMAX 1000000
#define HID 128

// ---------------- scratch (device globals; no runtime allocation) ------------
__device__ __align__(16) int   g_cnt[NMAX];
__device__ __align__(16) int   g_off[NMAX + 1];
__device__ __align__(16) int   g_cur[NMAX];
__device__ __align__(16) float g_dinv[NMAX];
__device__ __align__(16) int2  g_edge[EMAX];   // {src, w bits} interleaved
__device__ __align__(16) float g_buf1[(size_t)NMAX * HID];
__device__ __align__(16) float g_buf2[(size_t)NMAX * HID];
__device__ __align__(16) int   g_bsums[64];
__device__ int g_is64;

static inline int ceil_div(int a, int b) { return (a + b - 1) / b; }

// ---------------- helpers ----------------------------------------------------
__device__ __forceinline__ int load_idx(const void* p, int is64, long long i) {
    if (is64) return (int)((const long long*)p)[i];
    return ((const int*)p)[i];
}

__device__ __forceinline__ void split2(float2 v, uint32_t& hi, uint32_t& lo) {
    __nv_bfloat16 hx = __float2bfloat16(v.x), hy = __float2bfloat16(v.y);
    float rx = v.x - __bfloat162float(hx);
    float ry = v.y - __bfloat162float(hy);
    __nv_bfloat16 lx = __float2bfloat16(rx), ly = __float2bfloat16(ry);
    hi = ((uint32_t)__bfloat16_as_ushort(hy) << 16) | (uint32_t)__bfloat16_as_ushort(hx);
    lo = ((uint32_t)__bfloat16_as_ushort(ly) << 16) | (uint32_t)__bfloat16_as_ushort(lx);
}

__device__ __forceinline__ void mma_bf16(float& c0, float& c1, float& c2, float& c3,
                                         uint32_t a0, uint32_t a1, uint32_t a2, uint32_t a3,
                                         uint32_t b0, uint32_t b1) {
    asm volatile(
        "mma.sync.aligned.m16n8k16.row.col.f32.bf16.bf16.f32 "
        "{%0,%1,%2,%3}, {%4,%5,%6,%7}, {%8,%9}, {%0,%1,%2,%3};"
        : "+f"(c0), "+f"(c1), "+f"(c2), "+f"(c3)
        : "r"(a0), "r"(a1), "r"(a2), "r"(a3), "r"(b0), "r"(b1));
}

// ---------------- zero counters + dtype detect (fused) ------------------------
__global__ void k_zero_detect(const int* __restrict__ p, int nwords, int n) {
    int i = blockIdx.x * blockDim.x + threadIdx.x;
    if (i < n) g_cnt[i] = 0;
    if (blockIdx.x == 0 && threadIdx.x < 32) {
        bool oddzero = true;
        for (int j = threadIdx.x; j < 1024; j += 32) {
            int w = 2 * j + 1;
            if (w < nwords && p[w] != 0) oddzero = false;
        }
        oddzero = __all_sync(0xffffffffu, oddzero);
        if (threadIdx.x == 0) g_is64 = oddzero ? 1 : 0;
    }
}

__global__ void k_hist(const void* __restrict__ ei, int ne, int n) {
    int e = blockIdx.x * blockDim.x + threadIdx.x;
    int is64 = g_is64;
    if (e < ne) {
        int d = load_idx(ei, is64, (long long)ne + e);
        if (d >= 0 && d < n) atomicAdd(&g_cnt[d], 1);
    }
}

__global__ void k_scan1(int n) {
    __shared__ int sh[256];
    int tid  = threadIdx.x;
    int base = blockIdx.x * 2048;
    int vals[8];
    int tsum = 0;
#pragma unroll
    for (int v = 0; v < 8; v++) {
        int idx = base + tid * 8 + v;
        vals[v] = (idx < n) ? g_cnt[idx] : 0;
        tsum += vals[v];
    }
    sh[tid] = tsum;
    __syncthreads();
    for (int s = 1; s < 256; s <<= 1) {
        int t = (tid >= s) ? sh[tid - s] : 0;
        __syncthreads();
        sh[tid] += t;
        __syncthreads();
    }
    int run = sh[tid] - tsum;
    if (tid == 255) g_bsums[blockIdx.x] = sh[255];
#pragma unroll
    for (int v = 0; v < 8; v++) {
        int idx = base + tid * 8 + v;
        if (idx < n) g_off[idx] = run;
        run += vals[v];
    }
}

// scan3 with inline cross-block prefix (each 256-thr block lies in ONE 2048-group)
__global__ void k_scan3(int n, int ne) {
    __shared__ int pre;
    int b = blockIdx.x;
    int grp = b >> 3;
    if (threadIdx.x == 0) {
        int s = 0;
        for (int j = 0; j < grp; j++) s += g_bsums[j];
        pre = s;
    }
    __syncthreads();
    int i = b * 256 + threadIdx.x;
    if (i < n) {
        int o = g_off[i] + pre;
        g_off[i] = o;
        g_cur[i] = o;
        g_dinv[i] = rsqrtf((float)(g_cnt[i] + 1));  // +1 self loop
        if (i == 0) g_off[n] = ne;
    }
}

__global__ void k_fill(const void* __restrict__ ei, int ne, int n) {
    int e = blockIdx.x * blockDim.x + threadIdx.x;
    int is64 = g_is64;
    if (e < ne) {
        int s = load_idx(ei, is64, e);
        int d = load_idx(ei, is64, (long long)ne + e);
        if (s >= 0 && s < n && d >= 0 && d < n) {
            int p = atomicAdd(&g_cur[d], 1);
            g_edge[p] = make_int2(s, __float_as_int(g_dinv[s] * g_dinv[d]));
        }
    }
}

// ------- aggregation: Out[i] = sum norm_ij * X[j] + dinv_i^2 X[i] ------------
template <int F, int SRC, int DST>
__global__ void k_agg(const float* __restrict__ Xext, int n) {
    const float* X = (SRC == 0) ? Xext : (SRC == 1 ? g_buf1 : g_buf2);
    float* O       = (DST == 1) ? g_buf1 : g_buf2;
    int lane = threadIdx.x & 31, warp = threadIdx.x >> 5;
    int i = blockIdx.x * 8 + warp;
    if (i >= n) return;
    int e0 = g_off[i], e1 = g_off[i + 1];
    float di = g_dinv[i];
    float sw = di * di;

    if (F == 64) {
        float2 a0 = make_float2(0.f, 0.f), a1 = make_float2(0.f, 0.f);
        int e = e0;
        for (; e + 1 < e1; e += 2) {
            int2 ea = g_edge[e], eb = g_edge[e + 1];
            float wa = __int_as_float(ea.y), wb = __int_as_float(eb.y);
            float2 ha = ((const float2*)(X + (size_t)ea.x * 64))[lane];
            float2 hb = ((const float2*)(X + (size_t)eb.x * 64))[lane];
            a0.x = fmaf(wa, ha.x, a0.x); a0.y = fmaf(wa, ha.y, a0.y);
            a1.x = fmaf(wb, hb.x, a1.x); a1.y = fmaf(wb, hb.y, a1.y);
        }
        if (e < e1) {
            int2 ea = g_edge[e];
            float wa = __int_as_float(ea.y);
            float2 ha = ((const float2*)(X + (size_t)ea.x * 64))[lane];
            a0.x = fmaf(wa, ha.x, a0.x); a0.y = fmaf(wa, ha.y, a0.y);
        }
        float2 hs = ((const float2*)(X + (size_t)i * 64))[lane];
        float2 o;
        o.x = fmaf(sw, hs.x, a0.x + a1.x);
        o.y = fmaf(sw, hs.y, a0.y + a1.y);
        ((float2*)(O + (size_t)i * 64))[lane] = o;
    } else {
        float4 a0 = make_float4(0.f, 0.f, 0.f, 0.f), a1 = a0;
        int e = e0;
        for (; e + 1 < e1; e += 2) {
            int2 ea = g_edge[e], eb = g_edge[e + 1];
            float wa = __int_as_float(ea.y), wb = __int_as_float(eb.y);
            float4 ha = ((const float4*)(X + (size_t)ea.x * 128))[lane];
            float4 hb = ((const float4*)(X + (size_t)eb.x * 128))[lane];
            a0.x = fmaf(wa, ha.x, a0.x); a0.y = fmaf(wa, ha.y, a0.y);
            a0.z = fmaf(wa, ha.z, a0.z); a0.w = fmaf(wa, ha.w, a0.w);
            a1.x = fmaf(wb, hb.x, a1.x); a1.y = fmaf(wb, hb.y, a1.y);
            a1.z = fmaf(wb, hb.z, a1.z); a1.w = fmaf(wb, hb.w, a1.w);
        }
        if (e < e1) {
            int2 ea = g_edge[e];
            float wa = __int_as_float(ea.y);
            float4 ha = ((const float4*)(X + (size_t)ea.x * 128))[lane];
            a0.x = fmaf(wa, ha.x, a0.x); a0.y = fmaf(wa, ha.y, a0.y);
            a0.z = fmaf(wa, ha.z, a0.z); a0.w = fmaf(wa, ha.w, a0.w);
        }
        float4 hs = ((const float4*)(X + (size_t)i * 128))[lane];
        float4 o;
        o.x = fmaf(sw, hs.x, a0.x + a1.x);
        o.y = fmaf(sw, hs.y, a0.y + a1.y);
        o.z = fmaf(sw, hs.z, a0.z + a1.z);
        o.w = fmaf(sw, hs.w, a0.w + a1.w);
        ((float4*)(O + (size_t)i * 128))[lane] = o;
    }
}

// ------- bf16 split GEMM + bias + relu (layer 1): O[n,128] = relu(X@W + b) ---
// CTA: 128x128; 8 warps = 4(m) x 2(n); warp tile 32x64. 3 MMAs/frag pair.
template <int K, int SRC, int DST>
__global__ void __launch_bounds__(256)
k_gemm_mma(const float* __restrict__ W, const float* __restrict__ bias, int n) {
    __shared__ uint32_t XsHi[128 * 17], XsLo[128 * 17];
    __shared__ uint32_t WsHi[128 * 17], WsLo[128 * 17];

    const float* X = (SRC == 1) ? g_buf1 : g_buf2;
    float* O       = (DST == 1) ? g_buf1 : g_buf2;

    int tid = threadIdx.x, lane = tid & 31, warp = tid >> 5;
    int g = lane >> 2, t = lane & 3;
    int warp_m = warp & 3, warp_n = warp >> 2;
    int rb = blockIdx.x * 128;

    float c[2][8][4];
#pragma unroll
    for (int mi = 0; mi < 2; mi++)
#pragma unroll
        for (int nb = 0; nb < 8; nb++)
#pragma unroll
            for (int q = 0; q < 4; q++) c[mi][nb][q] = 0.f;

    const int NCH = K / 32;
    for (int ch = 0; ch < NCH; ch++) {
        int c0 = ch * 32;
        __syncthreads();
        for (int idx = tid; idx < 128 * 16; idx += 256) {
            int r = idx >> 4, kk = idx & 15;
            int row = rb + r;
            float2 v = (row < n) ? *(const float2*)(X + (size_t)row * K + c0 + 2 * kk)
                                 : make_float2(0.f, 0.f);
            uint32_t hi, lo;
            split2(v, hi, lo);
            XsHi[r * 17 + kk] = hi;
            XsLo[r * 17 + kk] = lo;
        }
        for (int idx = tid; idx < 128 * 16; idx += 256) {
            int kk = idx >> 7, nn = idx & 127;
            float2 v;
            v.x = W[(size_t)(c0 + 2 * kk) * 128 + nn];
            v.y = W[(size_t)(c0 + 2 * kk + 1) * 128 + nn];
            uint32_t hi, lo;
            split2(v, hi, lo);
            WsHi[nn * 17 + kk] = hi;
            WsLo[nn * 17 + kk] = lo;
        }
        __syncthreads();

#pragma unroll
        for (int step = 0; step < 2; step++) {
            int kb = step * 8;
            uint32_t bh0[8], bh1[8], bl0[8], bl1[8];
#pragma unroll
            for (int nb = 0; nb < 8; nb++) {
                int nl = warp_n * 64 + nb * 8 + g;
                bh0[nb] = WsHi[nl * 17 + kb + t];
                bh1[nb] = WsHi[nl * 17 + kb + t + 4];
                bl0[nb] = WsLo[nl * 17 + kb + t];
                bl1[nb] = WsLo[nl * 17 + kb + t + 4];
            }
#pragma unroll
            for (int mi = 0; mi < 2; mi++) {
                int rl = warp_m * 32 + mi * 16 + g;
                uint32_t ah0 = XsHi[rl * 17 + kb + t];
                uint32_t ah1 = XsHi[(rl + 8) * 17 + kb + t];
                uint32_t ah2 = XsHi[rl * 17 + kb + t + 4];
                uint32_t ah3 = XsHi[(rl + 8) * 17 + kb + t + 4];
                uint32_t al0 = XsLo[rl * 17 + kb + t];
                uint32_t al1 = XsLo[(rl + 8) * 17 + kb + t];
                uint32_t al2 = XsLo[rl * 17 + kb + t + 4];
                uint32_t al3 = XsLo[(rl + 8) * 17 + kb + t + 4];
#pragma unroll
                for (int nb = 0; nb < 8; nb++) {
                    mma_bf16(c[mi][nb][0], c[mi][nb][1], c[mi][nb][2], c[mi][nb][3],
                             ah0, ah1, ah2, ah3, bh0[nb], bh1[nb]);
                    mma_bf16(c[mi][nb][0], c[mi][nb][1], c[mi][nb][2], c[mi][nb][3],
                             ah0, ah1, ah2, ah3, bl0[nb], bl1[nb]);
                    mma_bf16(c[mi][nb][0], c[mi][nb][1], c[mi][nb][2], c[mi][nb][3],
                             al0, al1, al2, al3, bh0[nb], bh1[nb]);
                }
            }
        }
    }

#pragma unroll
    for (int mi = 0; mi < 2; mi++) {
        int row0 = rb + warp_m * 32 + mi * 16 + g;
        int row1 = row0 + 8;
#pragma unroll
        for (int nb = 0; nb < 8; nb++) {
            int col = warp_n * 64 + nb * 8 + 2 * t;
            float b0 = bias[col], b1 = bias[col + 1];
            if (row0 < n) {
                *(float2*)(O + (size_t)row0 * 128 + col) =
                    make_float2(fmaxf(c[mi][nb][0] + b0, 0.f), fmaxf(c[mi][nb][1] + b1, 0.f));
            }
            if (row1 < n) {
                *(float2*)(O + (size_t)row1 * 128 + col) =
                    make_float2(fmaxf(c[mi][nb][2] + b0, 0.f), fmaxf(c[mi][nb][3] + b1, 0.f));
            }
        }
    }
}

// ------- layer2 GEMM + bias + relu + head + log_softmax (fused, 128-tile) ----
// Same 128x128 tile & warp layout as k_gemm_mma. Dynamic smem:
//   [0,34816)       staging XsHi/XsLo/WsHi/WsLo (each 128*17 u32)
//   [0,67584)       H2 (128 x 132 f32) -- ALIASES staging, used post-mainloop
//   [67584,72704)   Wt (10x128 f32 transposed)
//   [72704,72744)   bls
#define SM2_TOTAL 72768
__global__ void __launch_bounds__(256)
k_gemm2_head(const float* __restrict__ W, const float* __restrict__ bias,
             const float* __restrict__ Wl, const float* __restrict__ bl,
             float* __restrict__ out, int n) {
    extern __shared__ __align__(16) char sm[];
    uint32_t* XsHi = (uint32_t*)(sm);
    uint32_t* XsLo = (uint32_t*)(sm + 8704);
    uint32_t* WsHi = (uint32_t*)(sm + 17408);
    uint32_t* WsLo = (uint32_t*)(sm + 26112);
    float*    H2   = (float*)(sm);          // alias; valid after mainloop
    float*    Wt   = (float*)(sm + 67584);
    float*    bls  = (float*)(sm + 72704);

    const float* X = g_buf1;
    const int K = 128;

    int tid = threadIdx.x, lane = tid & 31, warp = tid >> 5;
    int g = lane >> 2, t = lane & 3;
    int warp_m = warp & 3, warp_n = warp >> 2;
    int rb = blockIdx.x * 128;

    // stage head weights (non-aliased region) once
    for (int idx = tid; idx < 1280; idx += 256) {
        int k = idx / 10, j = idx - 10 * k;
        Wt[j * 128 + k] = Wl[idx];
    }
    if (tid < 10) bls[tid] = bl[tid];

    float c[2][8][4];
#pragma unroll
    for (int mi = 0; mi < 2; mi++)
#pragma unroll
        for (int nb = 0; nb < 8; nb++)
#pragma unroll
            for (int q = 0; q < 4; q++) c[mi][nb][q] = 0.f;

    for (int ch = 0; ch < 4; ch++) {
        int c0 = ch * 32;
        __syncthreads();
        for (int idx = tid; idx < 128 * 16; idx += 256) {
            int r = idx >> 4, kk = idx & 15;
            int row = rb + r;
            float2 v = (row < n) ? *(const float2*)(X + (size_t)row * K + c0 + 2 * kk)
                                 : make_float2(0.f, 0.f);
            uint32_t hi, lo;
            split2(v, hi, lo);
            XsHi[r * 17 + kk] = hi;
            XsLo[r * 17 + kk] = lo;
        }
        for (int idx = tid; idx < 128 * 16; idx += 256) {
            int kk = idx >> 7, nn = idx & 127;
            float2 v;
            v.x = W[(size_t)(c0 + 2 * kk) * 128 + nn];
            v.y = W[(size_t)(c0 + 2 * kk + 1) * 128 + nn];
            uint32_t hi, lo;
            split2(v, hi, lo);
            WsHi[nn * 17 + kk] = hi;
            WsLo[nn * 17 + kk] = lo;
        }
        __syncthreads();

#pragma unroll
        for (int step = 0; step < 2; step++) {
            int kb = step * 8;
            uint32_t bh0[8], bh1[8], bl0[8], bl1[8];
#pragma unroll
            for (int nb = 0; nb < 8; nb++) {
                int nl = warp_n * 64 + nb * 8 + g;
                bh0[nb] = WsHi[nl * 17 + kb + t];
                bh1[nb] = WsHi[nl * 17 + kb + t + 4];
                bl0[nb] = WsLo[nl * 17 + kb + t];
                bl1[nb] = WsLo[nl * 17 + kb + t + 4];
            }
#pragma unroll
            for (int mi = 0; mi < 2; mi++) {
                int rl = warp_m * 32 + mi * 16 + g;
                uint32_t ah0 = XsHi[rl * 17 + kb + t];
                uint32_t ah1 = XsHi[(rl + 8) * 17 + kb + t];
                uint32_t ah2 = XsHi[rl * 17 + kb + t + 4];
                uint32_t ah3 = XsHi[(rl + 8) * 17 + kb + t + 4];
                uint32_t al0 = XsLo[rl * 17 + kb + t];
                uint32_t al1 = XsLo[(rl + 8) * 17 + kb + t];
                uint32_t al2 = XsLo[rl * 17 + kb + t + 4];
                uint32_t al3 = XsLo[(rl + 8) * 17 + kb + t + 4];
#pragma unroll
                for (int nb = 0; nb < 8; nb++) {
                    mma_bf16(c[mi][nb][0], c[mi][nb][1], c[mi][nb][2], c[mi][nb][3],
                             ah0, ah1, ah2, ah3, bh0[nb], bh1[nb]);
                    mma_bf16(c[mi][nb][0], c[mi][nb][1], c[mi][nb][2], c[mi][nb][3],
                             ah0, ah1, ah2, ah3, bl0[nb], bl1[nb]);
                    mma_bf16(c[mi][nb][0], c[mi][nb][1], c[mi][nb][2], c[mi][nb][3],
                             al0, al1, al2, al3, bh0[nb], bh1[nb]);
                }
            }
        }
    }

    // epilogue: bias + relu into smem H2 (stride 132, conflict-free)
    __syncthreads();
#pragma unroll
    for (int mi = 0; mi < 2; mi++) {
        int r0 = warp_m * 32 + mi * 16 + g;
        int r1 = r0 + 8;
#pragma unroll
        for (int nb = 0; nb < 8; nb++) {
            int col = warp_n * 64 + nb * 8 + 2 * t;
            float b0 = bias[col], b1 = bias[col + 1];
            H2[r0 * 132 + col]     = fmaxf(c[mi][nb][0] + b0, 0.f);
            H2[r0 * 132 + col + 1] = fmaxf(c[mi][nb][1] + b1, 0.f);
            H2[r1 * 132 + col]     = fmaxf(c[mi][nb][2] + b0, 0.f);
            H2[r1 * 132 + col + 1] = fmaxf(c[mi][nb][3] + b1, 0.f);
        }
    }
    __syncthreads();

    // head: each warp handles 16 rows; log_softmax; write out only
    for (int it = 0; it < 16; it++) {
        int r = warp * 16 + it;
        int i = rb + r;
        if (i >= n) break;
        float4 hv = *(const float4*)(H2 + r * 132 + 4 * lane);
        float lg[10];
#pragma unroll
        for (int j = 0; j < 10; j++) {
            float4 wv = ((const float4*)(Wt + j * 128))[lane];
            float p = hv.x * wv.x + hv.y * wv.y + hv.z * wv.z + hv.w * wv.w;
#pragma unroll
            for (int o = 16; o; o >>= 1) p += __shfl_xor_sync(0xffffffffu, p, o);
            lg[j] = p + bls[j];
        }
        float m = lg[0];
#pragma unroll
        for (int j = 1; j < 10; j++) m = fmaxf(m, lg[j]);
        float s = 0.f;
#pragma unroll
        for (int j = 0; j < 10; j++) s += expf(lg[j] - m);
        float lse = m + logf(s);
        if (lane < 10) out[(size_t)i * 10 + lane] = lg[lane] - lse;
    }
}

// ---------------- launch -----------------------------------------------------
extern "C" void kernel_launch(void* const* d_in, const int* in_sizes, int n_in,
                              void* d_out, int out_size) {
    const float* x  = (const float*)d_in[0];
    const void*  ei = d_in[1];
    const float* W1 = (const float*)d_in[2];
    const float* b1 = (const float*)d_in[3];
    const float* W2 = (const float*)d_in[4];
    const float* b2 = (const float*)d_in[5];
    const float* Wl = (const float*)d_in[6];
    const float* bl = (const float*)d_in[7];
    float* out = (float*)d_out;

    int N = in_sizes[0] / 64;
    int E = in_sizes[1] / 2;

    static bool attr_done = false;
    if (!attr_done) {
        cudaFuncSetAttribute(k_gemm2_head, cudaFuncAttributeMaxDynamicSharedMemorySize, SM2_TOTAL);
        attr_done = true;
    }

    // --- CSR build ---
    k_zero_detect<<<ceil_div(N, 256), 256>>>((const int*)ei, 2 * E >= 2048 ? 2048 : 2 * E, N);
    k_hist<<<ceil_div(E, 256), 256>>>(ei, E, N);
    k_scan1<<<ceil_div(N, 2048), 256>>>(N);
    k_scan3<<<ceil_div(N, 256), 256>>>(N, E);
    k_fill<<<ceil_div(E, 256), 256>>>(ei, E, N);

    // --- layer 1 (agg-first): agg x (64) -> buf1; mma gemm -> buf2
    k_agg<64, 0, 1><<<ceil_div(N, 8), 256>>>(x, N);
    k_gemm_mma<64, 1, 2><<<ceil_div(N, 128), 256>>>(W1, b1, N);

    // --- layer 2: agg buf2 (128) -> buf1; fused 128-tile gemm+head -> out
    k_agg<128, 2, 1><<<ceil_div(N, 8), 256>>>(nullptr, N);
    k_gemm2_head<<<ceil_div(N, 128), 256, SM2_TOTAL>>>(W2, b2, Wl, bl, out, N);
}

// round 15
// speedup vs baseline: 1.0865x; 1.0611x over previous
#include <cuda_runtime.h>
#include <cuda_bf16.h>
#include <cuda_fp16.h>
#include <math.h>
#include <cstdint>

#define NMAX 100000
#define EMAX 1000000
#define HID 128

// ---------------- scratch (device globals; no runtime allocation) ------------
__device__ __align__(16) int    g_cnt[NMAX];
__device__ __align__(16) int    g_off[NMAX + 1];
__device__ __align__(16) int    g_cur[NMAX];
__device__ __align__(16) float  g_dinv[NMAX];
__device__ __align__(16) int2   g_edge[EMAX];            // {src, w bits}
__device__ __align__(16) float  g_buf1[(size_t)NMAX * 64];   // agg1 out (fp32, 64-wide)
__device__ __align__(16) __half g_ha[(size_t)NMAX * HID];    // H1 (fp16)
__device__ __align__(16) __half g_hb[(size_t)NMAX * HID];    // agg2 out (fp16)
__device__ __align__(16) int    g_bsums[64];
__device__ int g_is64;

static inline int ceil_div(int a, int b) { return (a + b - 1) / b; }

// ---------------- helpers ----------------------------------------------------
__device__ __forceinline__ int load_idx(const void* p, int is64, long long i) {
    if (is64) return (int)((const long long*)p)[i];
    return ((const int*)p)[i];
}

__device__ __forceinline__ void split2(float2 v, uint32_t& hi, uint32_t& lo) {
    __nv_bfloat16 hx = __float2bfloat16(v.x), hy = __float2bfloat16(v.y);
    float rx = v.x - __bfloat162float(hx);
    float ry = v.y - __bfloat162float(hy);
    __nv_bfloat16 lx = __float2bfloat16(rx), ly = __float2bfloat16(ry);
    hi = ((uint32_t)__bfloat16_as_ushort(hy) << 16) | (uint32_t)__bfloat16_as_ushort(hx);
    lo = ((uint32_t)__bfloat16_as_ushort(ly) << 16) | (uint32_t)__bfloat16_as_ushort(lx);
}

__device__ __forceinline__ void mma_bf16(float& c0, float& c1, float& c2, float& c3,
                                         uint32_t a0, uint32_t a1, uint32_t a2, uint32_t a3,
                                         uint32_t b0, uint32_t b1) {
    asm volatile(
        "mma.sync.aligned.m16n8k16.row.col.f32.bf16.bf16.f32 "
        "{%0,%1,%2,%3}, {%4,%5,%6,%7}, {%8,%9}, {%0,%1,%2,%3};"
        : "+f"(c0), "+f"(c1), "+f"(c2), "+f"(c3)
        : "r"(a0), "r"(a1), "r"(a2), "r"(a3), "r"(b0), "r"(b1));
}

// ---------------- zero counters + dtype detect (fused) ------------------------
__global__ void k_zero_detect(const int* __restrict__ p, int nwords, int n) {
    int i = blockIdx.x * blockDim.x + threadIdx.x;
    if (i < n) g_cnt[i] = 0;
    if (blockIdx.x == 0 && threadIdx.x < 32) {
        bool oddzero = true;
        for (int j = threadIdx.x; j < 1024; j += 32) {
            int w = 2 * j + 1;
            if (w < nwords && p[w] != 0) oddzero = false;
        }
        oddzero = __all_sync(0xffffffffu, oddzero);
        if (threadIdx.x == 0) g_is64 = oddzero ? 1 : 0;
    }
}

__global__ void k_hist(const void* __restrict__ ei, int ne, int n) {
    int e = blockIdx.x * blockDim.x + threadIdx.x;
    int is64 = g_is64;
    if (e < ne) {
        int d = load_idx(ei, is64, (long long)ne + e);
        if (d >= 0 && d < n) atomicAdd(&g_cnt[d], 1);
    }
}

__global__ void k_scan1(int n) {
    __shared__ int sh[256];
    int tid  = threadIdx.x;
    int base = blockIdx.x * 2048;
    int vals[8];
    int tsum = 0;
#pragma unroll
    for (int v = 0; v < 8; v++) {
        int idx = base + tid * 8 + v;
        vals[v] = (idx < n) ? g_cnt[idx] : 0;
        tsum += vals[v];
    }
    sh[tid] = tsum;
    __syncthreads();
    for (int s = 1; s < 256; s <<= 1) {
        int t = (tid >= s) ? sh[tid - s] : 0;
        __syncthreads();
        sh[tid] += t;
        __syncthreads();
    }
    int run = sh[tid] - tsum;
    if (tid == 255) g_bsums[blockIdx.x] = sh[255];
#pragma unroll
    for (int v = 0; v < 8; v++) {
        int idx = base + tid * 8 + v;
        if (idx < n) g_off[idx] = run;
        run += vals[v];
    }
}

// scan3: parallel prefix over g_bsums (64 lanes + shfl reduce, no serial L2 walk)
__global__ void k_scan3(int n, int ne) {
    __shared__ int wsum[2];
    int tid = threadIdx.x;
    int b = blockIdx.x;
    int grp = b >> 3;
    if (tid < 64) {
        int v = (tid < grp) ? g_bsums[tid] : 0;
#pragma unroll
        for (int o = 16; o; o >>= 1) v += __shfl_down_sync(0xffffffffu, v, o);
        if ((tid & 31) == 0) wsum[tid >> 5] = v;
    }
    __syncthreads();
    int pre = wsum[0] + wsum[1];
    int i = b * 256 + tid;
    if (i < n) {
        int o = g_off[i] + pre;
        g_off[i] = o;
        g_cur[i] = o;
        g_dinv[i] = rsqrtf((float)(g_cnt[i] + 1));  // +1 self loop
        if (i == 0) g_off[n] = ne;
    }
}

__global__ void k_fill(const void* __restrict__ ei, int ne, int n) {
    int e = blockIdx.x * blockDim.x + threadIdx.x;
    int is64 = g_is64;
    if (e < ne) {
        int s = load_idx(ei, is64, e);
        int d = load_idx(ei, is64, (long long)ne + e);
        if (s >= 0 && s < n && d >= 0 && d < n) {
            int p = atomicAdd(&g_cur[d], 1);
            g_edge[p] = make_int2(s, __float_as_int(g_dinv[s] * g_dinv[d]));
        }
    }
}

// ------- agg1 (fp32 in, fp32 out, 64-wide): Out[i] = sum norm*X[j] + dinv^2 X[i]
__global__ void k_agg1(const float* __restrict__ X, int n) {
    int lane = threadIdx.x & 31, warp = threadIdx.x >> 5;
    int i = blockIdx.x * 8 + warp;
    if (i >= n) return;
    int e0 = g_off[i], e1 = g_off[i + 1];
    float di = g_dinv[i];
    float sw = di * di;

    float2 a0 = make_float2(0.f, 0.f), a1 = make_float2(0.f, 0.f);
    int e = e0;
    for (; e + 1 < e1; e += 2) {
        int2 ea = g_edge[e], eb = g_edge[e + 1];
        float wa = __int_as_float(ea.y), wb = __int_as_float(eb.y);
        float2 ha = ((const float2*)(X + (size_t)ea.x * 64))[lane];
        float2 hb = ((const float2*)(X + (size_t)eb.x * 64))[lane];
        a0.x = fmaf(wa, ha.x, a0.x); a0.y = fmaf(wa, ha.y, a0.y);
        a1.x = fmaf(wb, hb.x, a1.x); a1.y = fmaf(wb, hb.y, a1.y);
    }
    if (e < e1) {
        int2 ea = g_edge[e];
        float wa = __int_as_float(ea.y);
        float2 ha = ((const float2*)(X + (size_t)ea.x * 64))[lane];
        a0.x = fmaf(wa, ha.x, a0.x); a0.y = fmaf(wa, ha.y, a0.y);
    }
    float2 hs = ((const float2*)(X + (size_t)i * 64))[lane];
    float2 o;
    o.x = fmaf(sw, hs.x, a0.x + a1.x);
    o.y = fmaf(sw, hs.y, a0.y + a1.y);
    ((float2*)(g_buf1 + (size_t)i * 64))[lane] = o;
}

// ------- agg2 (fp16 in/out, 128-wide): g_hb[i] = sum norm*g_ha[j] + dinv^2 g_ha[i]
__global__ void k_agg2(int n) {
    int lane = threadIdx.x & 31, warp = threadIdx.x >> 5;
    int i = blockIdx.x * 8 + warp;
    if (i >= n) return;
    int e0 = g_off[i], e1 = g_off[i + 1];
    float di = g_dinv[i];
    float sw = di * di;

    float4 a0 = make_float4(0.f, 0.f, 0.f, 0.f), a1 = a0;
    int e = e0;
    for (; e + 1 < e1; e += 2) {
        int2 ea = g_edge[e], eb = g_edge[e + 1];
        float wa = __int_as_float(ea.y), wb = __int_as_float(eb.y);
        uint2 ra = *(const uint2*)(g_ha + (size_t)ea.x * 128 + 4 * lane);
        uint2 rb = *(const uint2*)(g_ha + (size_t)eb.x * 128 + 4 * lane);
        float2 fa0 = __half22float2(*(__half2*)&ra.x), fa1 = __half22float2(*(__half2*)&ra.y);
        float2 fb0 = __half22float2(*(__half2*)&rb.x), fb1 = __half22float2(*(__half2*)&rb.y);
        a0.x = fmaf(wa, fa0.x, a0.x); a0.y = fmaf(wa, fa0.y, a0.y);
        a0.z = fmaf(wa, fa1.x, a0.z); a0.w = fmaf(wa, fa1.y, a0.w);
        a1.x = fmaf(wb, fb0.x, a1.x); a1.y = fmaf(wb, fb0.y, a1.y);
        a1.z = fmaf(wb, fb1.x, a1.z); a1.w = fmaf(wb, fb1.y, a1.w);
    }
    if (e < e1) {
        int2 ea = g_edge[e];
        float wa = __int_as_float(ea.y);
        uint2 ra = *(const uint2*)(g_ha + (size_t)ea.x * 128 + 4 * lane);
        float2 fa0 = __half22float2(*(__half2*)&ra.x), fa1 = __half22float2(*(__half2*)&ra.y);
        a0.x = fmaf(wa, fa0.x, a0.x); a0.y = fmaf(wa, fa0.y, a0.y);
        a0.z = fmaf(wa, fa1.x, a0.z); a0.w = fmaf(wa, fa1.y, a0.w);
    }
    uint2 rs = *(const uint2*)(g_ha + (size_t)i * 128 + 4 * lane);
    float2 fs0 = __half22float2(*(__half2*)&rs.x), fs1 = __half22float2(*(__half2*)&rs.y);
    float ox = fmaf(sw, fs0.x, a0.x + a1.x);
    float oy = fmaf(sw, fs0.y, a0.y + a1.y);
    float oz = fmaf(sw, fs1.x, a0.z + a1.z);
    float ow = fmaf(sw, fs1.y, a0.w + a1.w);
    uint2 st;
    *(__half2*)&st.x = __floats2half2_rn(ox, oy);
    *(__half2*)&st.y = __floats2half2_rn(oz, ow);
    *(uint2*)(g_hb + (size_t)i * 128 + 4 * lane) = st;
}

// ------- layer1 GEMM: g_ha[n,128] = relu(g_buf1[n,64] @ W + b)  (fp16 out) ---
// CTA: 128x128; 8 warps = 4(m) x 2(n); warp tile 32x64. 3 MMAs/frag pair.
__global__ void __launch_bounds__(256)
k_gemm1(const float* __restrict__ W, const float* __restrict__ bias, int n) {
    __shared__ uint32_t XsHi[128 * 17], XsLo[128 * 17];
    __shared__ uint32_t WsHi[128 * 17], WsLo[128 * 17];
    const int K = 64;

    int tid = threadIdx.x, lane = tid & 31, warp = tid >> 5;
    int g = lane >> 2, t = lane & 3;
    int warp_m = warp & 3, warp_n = warp >> 2;
    int rb = blockIdx.x * 128;

    float c[2][8][4];
#pragma unroll
    for (int mi = 0; mi < 2; mi++)
#pragma unroll
        for (int nb = 0; nb < 8; nb++)
#pragma unroll
            for (int q = 0; q < 4; q++) c[mi][nb][q] = 0.f;

    for (int ch = 0; ch < 2; ch++) {
        int c0 = ch * 32;
        __syncthreads();
        for (int idx = tid; idx < 128 * 16; idx += 256) {
            int r = idx >> 4, kk = idx & 15;
            int row = rb + r;
            float2 v = (row < n) ? *(const float2*)(g_buf1 + (size_t)row * K + c0 + 2 * kk)
                                 : make_float2(0.f, 0.f);
            uint32_t hi, lo;
            split2(v, hi, lo);
            XsHi[r * 17 + kk] = hi;
            XsLo[r * 17 + kk] = lo;
        }
        for (int idx = tid; idx < 128 * 16; idx += 256) {
            int kk = idx >> 7, nn = idx & 127;
            float2 v;
            v.x = W[(size_t)(c0 + 2 * kk) * 128 + nn];
            v.y = W[(size_t)(c0 + 2 * kk + 1) * 128 + nn];
            uint32_t hi, lo;
            split2(v, hi, lo);
            WsHi[nn * 17 + kk] = hi;
            WsLo[nn * 17 + kk] = lo;
        }
        __syncthreads();

#pragma unroll
        for (int step = 0; step < 2; step++) {
            int kb = step * 8;
            uint32_t bh0[8], bh1[8], bl0[8], bl1[8];
#pragma unroll
            for (int nb = 0; nb < 8; nb++) {
                int nl = warp_n * 64 + nb * 8 + g;
                bh0[nb] = WsHi[nl * 17 + kb + t];
                bh1[nb] = WsHi[nl * 17 + kb + t + 4];
                bl0[nb] = WsLo[nl * 17 + kb + t];
                bl1[nb] = WsLo[nl * 17 + kb + t + 4];
            }
#pragma unroll
            for (int mi = 0; mi < 2; mi++) {
                int rl = warp_m * 32 + mi * 16 + g;
                uint32_t ah0 = XsHi[rl * 17 + kb + t];
                uint32_t ah1 = XsHi[(rl + 8) * 17 + kb + t];
                uint32_t ah2 = XsHi[rl * 17 + kb + t + 4];
                uint32_t ah3 = XsHi[(rl + 8) * 17 + kb + t + 4];
                uint32_t al0 = XsLo[rl * 17 + kb + t];
                uint32_t al1 = XsLo[(rl + 8) * 17 + kb + t];
                uint32_t al2 = XsLo[rl * 17 + kb + t + 4];
                uint32_t al3 = XsLo[(rl + 8) * 17 + kb + t + 4];
#pragma unroll
                for (int nb = 0; nb < 8; nb++) {
                    mma_bf16(c[mi][nb][0], c[mi][nb][1], c[mi][nb][2], c[mi][nb][3],
                             ah0, ah1, ah2, ah3, bh0[nb], bh1[nb]);
                    mma_bf16(c[mi][nb][0], c[mi][nb][1], c[mi][nb][2], c[mi][nb][3],
                             ah0, ah1, ah2, ah3, bl0[nb], bl1[nb]);
                    mma_bf16(c[mi][nb][0], c[mi][nb][1], c[mi][nb][2], c[mi][nb][3],
                             al0, al1, al2, al3, bh0[nb], bh1[nb]);
                }
            }
        }
    }

#pragma unroll
    for (int mi = 0; mi < 2; mi++) {
        int row0 = rb + warp_m * 32 + mi * 16 + g;
        int row1 = row0 + 8;
#pragma unroll
        for (int nb = 0; nb < 8; nb++) {
            int col = warp_n * 64 + nb * 8 + 2 * t;
            float b0 = bias[col], b1 = bias[col + 1];
            if (row0 < n) {
                __half2 h = __floats2half2_rn(fmaxf(c[mi][nb][0] + b0, 0.f),
                                              fmaxf(c[mi][nb][1] + b1, 0.f));
                *(__half2*)(g_ha + (size_t)row0 * 128 + col) = h;
            }
            if (row1 < n) {
                __half2 h = __floats2half2_rn(fmaxf(c[mi][nb][2] + b0, 0.f),
                                              fmaxf(c[mi][nb][3] + b1, 0.f));
                *(__half2*)(g_ha + (size_t)row1 * 128 + col) = h;
            }
        }
    }
}

// ------- layer2 GEMM + bias + relu + head + log_softmax (fused, 128-tile) ----
// A from g_hb (fp16). Dynamic smem:
//   [0,34816)       staging XsHi/XsLo/WsHi/WsLo (each 128*17 u32)
//   [0,67584)       H2 (128 x 132 f32) -- aliases staging, post-mainloop
//   [67584,72704)   Wt (10x128 f32 transposed)
//   [72704,72744)   bls
#define SM2_TOTAL 72768
__global__ void __launch_bounds__(256)
k_gemm2_head(const float* __restrict__ W, const float* __restrict__ bias,
             const float* __restrict__ Wl, const float* __restrict__ bl,
             float* __restrict__ out, int n) {
    extern __shared__ __align__(16) char sm[];
    uint32_t* XsHi = (uint32_t*)(sm);
    uint32_t* XsLo = (uint32_t*)(sm + 8704);
    uint32_t* WsHi = (uint32_t*)(sm + 17408);
    uint32_t* WsLo = (uint32_t*)(sm + 26112);
    float*    H2   = (float*)(sm);
    float*    Wt   = (float*)(sm + 67584);
    float*    bls  = (float*)(sm + 72704);

    const int K = 128;
    int tid = threadIdx.x, lane = tid & 31, warp = tid >> 5;
    int g = lane >> 2, t = lane & 3;
    int warp_m = warp & 3, warp_n = warp >> 2;
    int rb = blockIdx.x * 128;

    for (int idx = tid; idx < 1280; idx += 256) {
        int k = idx / 10, j = idx - 10 * k;
        Wt[j * 128 + k] = Wl[idx];
    }
    if (tid < 10) bls[tid] = bl[tid];

    float c[2][8][4];
#pragma unroll
    for (int mi = 0; mi < 2; mi++)
#pragma unroll
        for (int nb = 0; nb < 8; nb++)
#pragma unroll
            for (int q = 0; q < 4; q++) c[mi][nb][q] = 0.f;

    for (int ch = 0; ch < 4; ch++) {
        int c0 = ch * 32;
        __syncthreads();
        for (int idx = tid; idx < 128 * 16; idx += 256) {
            int r = idx >> 4, kk = idx & 15;
            int row = rb + r;
            float2 v = make_float2(0.f, 0.f);
            if (row < n) {
                uint32_t raw = ((const uint32_t*)(g_hb + (size_t)row * K))[c0 / 2 + kk];
                v = __half22float2(*(__half2*)&raw);
            }
            uint32_t hi, lo;
            split2(v, hi, lo);
            XsHi[r * 17 + kk] = hi;
            XsLo[r * 17 + kk] = lo;
        }
        for (int idx = tid; idx < 128 * 16; idx += 256) {
            int kk = idx >> 7, nn = idx & 127;
            float2 v;
            v.x = W[(size_t)(c0 + 2 * kk) * 128 + nn];
            v.y = W[(size_t)(c0 + 2 * kk + 1) * 128 + nn];
            uint32_t hi, lo;
            split2(v, hi, lo);
            WsHi[nn * 17 + kk] = hi;
            WsLo[nn * 17 + kk] = lo;
        }
        __syncthreads();

#pragma unroll
        for (int step = 0; step < 2; step++) {
            int kb = step * 8;
            uint32_t bh0[8], bh1[8], bl0[8], bl1[8];
#pragma unroll
            for (int nb = 0; nb < 8; nb++) {
                int nl = warp_n * 64 + nb * 8 + g;
                bh0[nb] = WsHi[nl * 17 + kb + t];
                bh1[nb] = WsHi[nl * 17 + kb + t + 4];
                bl0[nb] = WsLo[nl * 17 + kb + t];
                bl1[nb] = WsLo[nl * 17 + kb + t + 4];
            }
#pragma unroll
            for (int mi = 0; mi < 2; mi++) {
                int rl = warp_m * 32 + mi * 16 + g;
                uint32_t ah0 = XsHi[rl * 17 + kb + t];
                uint32_t ah1 = XsHi[(rl + 8) * 17 + kb + t];
                uint32_t ah2 = XsHi[rl * 17 + kb + t + 4];
                uint32_t ah3 = XsHi[(rl + 8) * 17 + kb + t + 4];
                uint32_t al0 = XsLo[rl * 17 + kb + t];
                uint32_t al1 = XsLo[(rl + 8) * 17 + kb + t];
                uint32_t al2 = XsLo[rl * 17 + kb + t + 4];
                uint32_t al3 = XsLo[(rl + 8) * 17 + kb + t + 4];
#pragma unroll
                for (int nb = 0; nb < 8; nb++) {
                    mma_bf16(c[mi][nb][0], c[mi][nb][1], c[mi][nb][2], c[mi][nb][3],
                             ah0, ah1, ah2, ah3, bh0[nb], bh1[nb]);
                    mma_bf16(c[mi][nb][0], c[mi][nb][1], c[mi][nb][2], c[mi][nb][3],
                             ah0, ah1, ah2, ah3, bl0[nb], bl1[nb]);
                    mma_bf16(c[mi][nb][0], c[mi][nb][1], c[mi][nb][2], c[mi][nb][3],
                             al0, al1, al2, al3, bh0[nb], bh1[nb]);
                }
            }
        }
    }

    // epilogue: bias + relu into smem H2 (stride 132, conflict-free)
    __syncthreads();
#pragma unroll
    for (int mi = 0; mi < 2; mi++) {
        int r0 = warp_m * 32 + mi * 16 + g;
        int r1 = r0 + 8;
#pragma unroll
        for (int nb = 0; nb < 8; nb++) {
            int col = warp_n * 64 + nb * 8 + 2 * t;
            float b0 = bias[col], b1 = bias[col + 1];
            H2[r0 * 132 + col]     = fmaxf(c[mi][nb][0] + b0, 0.f);
            H2[r0 * 132 + col + 1] = fmaxf(c[mi][nb][1] + b1, 0.f);
            H2[r1 * 132 + col]     = fmaxf(c[mi][nb][2] + b0, 0.f);
            H2[r1 * 132 + col + 1] = fmaxf(c[mi][nb][3] + b1, 0.f);
        }
    }
    __syncthreads();

    // head: each warp handles 16 rows; log_softmax; write out only
    for (int it = 0; it < 16; it++) {
        int r = warp * 16 + it;
        int i = rb + r;
        if (i >= n) break;
        float4 hv = *(const float4*)(H2 + r * 132 + 4 * lane);
        float lg[10];
#pragma unroll
        for (int j = 0; j < 10; j++) {
            float4 wv = ((const float4*)(Wt + j * 128))[lane];
            float p = hv.x * wv.x + hv.y * wv.y + hv.z * wv.z + hv.w * wv.w;
#pragma unroll
            for (int o = 16; o; o >>= 1) p += __shfl_xor_sync(0xffffffffu, p, o);
            lg[j] = p + bls[j];
        }
        float m = lg[0];
#pragma unroll
        for (int j = 1; j < 10; j++) m = fmaxf(m, lg[j]);
        float s = 0.f;
#pragma unroll
        for (int j = 0; j < 10; j++) s += expf(lg[j] - m);
        float lse = m + logf(s);
        if (lane < 10) out[(size_t)i * 10 + lane] = lg[lane] - lse;
    }
}

// ---------------- launch -----------------------------------------------------
extern "C" void kernel_launch(void* const* d_in, const int* in_sizes, int n_in,
                              void* d_out, int out_size) {
    const float* x  = (const float*)d_in[0];
    const void*  ei = d_in[1];
    const float* W1 = (const float*)d_in[2];
    const float* b1 = (const float*)d_in[3];
    const float* W2 = (const float*)d_in[4];
    const float* b2 = (const float*)d_in[5];
    const float* Wl = (const float*)d_in[6];
    const float* bl = (const float*)d_in[7];
    float* out = (float*)d_out;

    int N = in_sizes[0] / 64;
    int E = in_sizes[1] / 2;

    static bool attr_done = false;
    if (!attr_done) {
        cudaFuncSetAttribute(k_gemm2_head, cudaFuncAttributeMaxDynamicSharedMemorySize, SM2_TOTAL);
        attr_done = true;
    }

    // --- CSR build ---
    k_zero_detect<<<ceil_div(N, 256), 256>>>((const int*)ei, 2 * E >= 2048 ? 2048 : 2 * E, N);
    k_hist<<<ceil_div(E, 256), 256>>>(ei, E, N);
    k_scan1<<<ceil_div(N, 2048), 256>>>(N);
    k_scan3<<<ceil_div(N, 256), 256>>>(N, E);
    k_fill<<<ceil_div(E, 256), 256>>>(ei, E, N);

    // --- layer 1 (agg-first): agg x (64,fp32) -> g_buf1; gemm -> g_ha (fp16)
    k_agg1<<<ceil_div(N, 8), 256>>>(x, N);
    k_gemm1<<<ceil_div(N, 128), 256>>>(W1, b1, N);

    // --- layer 2: agg g_ha (fp16) -> g_hb (fp16); fused gemm+head -> out
    k_agg2<<<ceil_div(N, 8), 256>>>(N);
    k_gemm2_head<<<ceil_div(N, 128), 256, SM2_TOTAL>>>(W2, b2, Wl, bl, out, N);
}

// round 16
// speedup vs baseline: 1.1585x; 1.0662x over previous
#include <cuda_runtime.h>
#include <cuda_bf16.h>
#include <cuda_fp16.h>
#include <math.h>
#include <cstdint>

#define NMAX 100000
#define EMAX 1000000
#define HID 128

// ---------------- scratch (device globals; no runtime allocation) ------------
__device__ __align__(16) int    g_cnt[NMAX];
__device__ __align__(16) int    g_off[NMAX + 1];
__device__ __align__(16) int    g_cur[NMAX];
__device__ __align__(16) float  g_dinv[NMAX];
__device__ __align__(16) int2   g_edge[EMAX];              // {src, w bits}
__device__ __align__(16) __half g_b1h[(size_t)NMAX * 64];  // agg1 out (fp16, 64-wide)
__device__ __align__(16) __half g_ha[(size_t)NMAX * HID];  // H1 (fp16)
__device__ __align__(16) __half g_hb[(size_t)NMAX * HID];  // agg2 out (fp16)
__device__ __align__(16) int    g_bsums[64];
__device__ int g_is64;

static inline int ceil_div(int a, int b) { return (a + b - 1) / b; }

// ---------------- helpers ----------------------------------------------------
__device__ __forceinline__ int load_idx(const void* p, int is64, long long i) {
    if (is64) return (int)((const long long*)p)[i];
    return ((const int*)p)[i];
}

// split a float2 into packed fp16x2 hi and lo words (W path; err ~2^-22)
__device__ __forceinline__ void split2h(float2 v, uint32_t& hi, uint32_t& lo) {
    __half hx = __float2half_rn(v.x), hy = __float2half_rn(v.y);
    float rx = v.x - __half2float(hx);
    float ry = v.y - __half2float(hy);
    __half lx = __float2half_rn(rx), ly = __float2half_rn(ry);
    hi = ((uint32_t)__half_as_ushort(hy) << 16) | (uint32_t)__half_as_ushort(hx);
    lo = ((uint32_t)__half_as_ushort(ly) << 16) | (uint32_t)__half_as_ushort(lx);
}

__device__ __forceinline__ void mma_f16(float& c0, float& c1, float& c2, float& c3,
                                        uint32_t a0, uint32_t a1, uint32_t a2, uint32_t a3,
                                        uint32_t b0, uint32_t b1) {
    asm volatile(
        "mma.sync.aligned.m16n8k16.row.col.f32.f16.f16.f32 "
        "{%0,%1,%2,%3}, {%4,%5,%6,%7}, {%8,%9}, {%0,%1,%2,%3};"
        : "+f"(c0), "+f"(c1), "+f"(c2), "+f"(c3)
        : "r"(a0), "r"(a1), "r"(a2), "r"(a3), "r"(b0), "r"(b1));
}

// ---------------- zero counters + dtype detect (fused) ------------------------
__global__ void k_zero_detect(const int* __restrict__ p, int nwords, int n) {
    int i = blockIdx.x * blockDim.x + threadIdx.x;
    if (i < n) g_cnt[i] = 0;
    if (blockIdx.x == 0 && threadIdx.x < 32) {
        bool oddzero = true;
        for (int j = threadIdx.x; j < 1024; j += 32) {
            int w = 2 * j + 1;
            if (w < nwords && p[w] != 0) oddzero = false;
        }
        oddzero = __all_sync(0xffffffffu, oddzero);
        if (threadIdx.x == 0) g_is64 = oddzero ? 1 : 0;
    }
}

__global__ void k_hist(const void* __restrict__ ei, int ne, int n) {
    int e = blockIdx.x * blockDim.x + threadIdx.x;
    int is64 = g_is64;
    if (e < ne) {
        int d = load_idx(ei, is64, (long long)ne + e);
        if (d >= 0 && d < n) atomicAdd(&g_cnt[d], 1);
    }
}

__global__ void k_scan1(int n) {
    __shared__ int sh[256];
    int tid  = threadIdx.x;
    int base = blockIdx.x * 2048;
    int vals[8];
    int tsum = 0;
#pragma unroll
    for (int v = 0; v < 8; v++) {
        int idx = base + tid * 8 + v;
        vals[v] = (idx < n) ? g_cnt[idx] : 0;
        tsum += vals[v];
    }
    sh[tid] = tsum;
    __syncthreads();
    for (int s = 1; s < 256; s <<= 1) {
        int t = (tid >= s) ? sh[tid - s] : 0;
        __syncthreads();
        sh[tid] += t;
        __syncthreads();
    }
    int run = sh[tid] - tsum;
    if (tid == 255) g_bsums[blockIdx.x] = sh[255];
#pragma unroll
    for (int v = 0; v < 8; v++) {
        int idx = base + tid * 8 + v;
        if (idx < n) g_off[idx] = run;
        run += vals[v];
    }
}

// scan3: parallel prefix over g_bsums (64 lanes + shfl reduce)
__global__ void k_scan3(int n, int ne) {
    __shared__ int wsum[2];
    int tid = threadIdx.x;
    int b = blockIdx.x;
    int grp = b >> 3;
    if (tid < 64) {
        int v = (tid < grp) ? g_bsums[tid] : 0;
#pragma unroll
        for (int o = 16; o; o >>= 1) v += __shfl_down_sync(0xffffffffu, v, o);
        if ((tid & 31) == 0) wsum[tid >> 5] = v;
    }
    __syncthreads();
    int pre = wsum[0] + wsum[1];
    int i = b * 256 + tid;
    if (i < n) {
        int o = g_off[i] + pre;
        g_off[i] = o;
        g_cur[i] = o;
        g_dinv[i] = rsqrtf((float)(g_cnt[i] + 1));  // +1 self loop
        if (i == 0) g_off[n] = ne;
    }
}

__global__ void k_fill(const void* __restrict__ ei, int ne, int n) {
    int e = blockIdx.x * blockDim.x + threadIdx.x;
    int is64 = g_is64;
    if (e < ne) {
        int s = load_idx(ei, is64, e);
        int d = load_idx(ei, is64, (long long)ne + e);
        if (s >= 0 && s < n && d >= 0 && d < n) {
            int p = atomicAdd(&g_cur[d], 1);
            g_edge[p] = make_int2(s, __float_as_int(g_dinv[s] * g_dinv[d]));
        }
    }
}

// ------- agg1 (fp32 in, fp16 out, 64-wide): Out[i] = sum norm*X[j] + dinv^2 X[i]
__global__ void k_agg1(const float* __restrict__ X, int n) {
    int lane = threadIdx.x & 31, warp = threadIdx.x >> 5;
    int i = blockIdx.x * 8 + warp;
    if (i >= n) return;
    int e0 = g_off[i], e1 = g_off[i + 1];
    float di = g_dinv[i];
    float sw = di * di;

    float2 a0 = make_float2(0.f, 0.f), a1 = make_float2(0.f, 0.f);
    int e = e0;
    for (; e + 1 < e1; e += 2) {
        int2 ea = g_edge[e], eb = g_edge[e + 1];
        float wa = __int_as_float(ea.y), wb = __int_as_float(eb.y);
        float2 ha = ((const float2*)(X + (size_t)ea.x * 64))[lane];
        float2 hb = ((const float2*)(X + (size_t)eb.x * 64))[lane];
        a0.x = fmaf(wa, ha.x, a0.x); a0.y = fmaf(wa, ha.y, a0.y);
        a1.x = fmaf(wb, hb.x, a1.x); a1.y = fmaf(wb, hb.y, a1.y);
    }
    if (e < e1) {
        int2 ea = g_edge[e];
        float wa = __int_as_float(ea.y);
        float2 ha = ((const float2*)(X + (size_t)ea.x * 64))[lane];
        a0.x = fmaf(wa, ha.x, a0.x); a0.y = fmaf(wa, ha.y, a0.y);
    }
    float2 hs = ((const float2*)(X + (size_t)i * 64))[lane];
    float ox = fmaf(sw, hs.x, a0.x + a1.x);
    float oy = fmaf(sw, hs.y, a0.y + a1.y);
    *(__half2*)(g_b1h + (size_t)i * 64 + 2 * lane) = __floats2half2_rn(ox, oy);
}

// ------- agg2 (fp16 in/out, 128-wide): g_hb[i] = sum norm*g_ha[j] + dinv^2 g_ha[i]
__global__ void k_agg2(int n) {
    int lane = threadIdx.x & 31, warp = threadIdx.x >> 5;
    int i = blockIdx.x * 8 + warp;
    if (i >= n) return;
    int e0 = g_off[i], e1 = g_off[i + 1];
    float di = g_dinv[i];
    float sw = di * di;

    float4 a0 = make_float4(0.f, 0.f, 0.f, 0.f), a1 = a0;
    int e = e0;
    for (; e + 1 < e1; e += 2) {
        int2 ea = g_edge[e], eb = g_edge[e + 1];
        float wa = __int_as_float(ea.y), wb = __int_as_float(eb.y);
        uint2 ra = *(const uint2*)(g_ha + (size_t)ea.x * 128 + 4 * lane);
        uint2 rb = *(const uint2*)(g_ha + (size_t)eb.x * 128 + 4 * lane);
        float2 fa0 = __half22float2(*(__half2*)&ra.x), fa1 = __half22float2(*(__half2*)&ra.y);
        float2 fb0 = __half22float2(*(__half2*)&rb.x), fb1 = __half22float2(*(__half2*)&rb.y);
        a0.x = fmaf(wa, fa0.x, a0.x); a0.y = fmaf(wa, fa0.y, a0.y);
        a0.z = fmaf(wa, fa1.x, a0.z); a0.w = fmaf(wa, fa1.y, a0.w);
        a1.x = fmaf(wb, fb0.x, a1.x); a1.y = fmaf(wb, fb0.y, a1.y);
        a1.z = fmaf(wb, fb1.x, a1.z); a1.w = fmaf(wb, fb1.y, a1.w);
    }
    if (e < e1) {
        int2 ea = g_edge[e];
        float wa = __int_as_float(ea.y);
        uint2 ra = *(const uint2*)(g_ha + (size_t)ea.x * 128 + 4 * lane);
        float2 fa0 = __half22float2(*(__half2*)&ra.x), fa1 = __half22float2(*(__half2*)&ra.y);
        a0.x = fmaf(wa, fa0.x, a0.x); a0.y = fmaf(wa, fa0.y, a0.y);
        a0.z = fmaf(wa, fa1.x, a0.z); a0.w = fmaf(wa, fa1.y, a0.w);
    }
    uint2 rs = *(const uint2*)(g_ha + (size_t)i * 128 + 4 * lane);
    float2 fs0 = __half22float2(*(__half2*)&rs.x), fs1 = __half22float2(*(__half2*)&rs.y);
    float ox = fmaf(sw, fs0.x, a0.x + a1.x);
    float oy = fmaf(sw, fs0.y, a0.y + a1.y);
    float oz = fmaf(sw, fs1.x, a0.z + a1.z);
    float ow = fmaf(sw, fs1.y, a0.w + a1.w);
    uint2 st;
    *(__half2*)&st.x = __floats2half2_rn(ox, oy);
    *(__half2*)&st.y = __floats2half2_rn(oz, ow);
    *(uint2*)(g_hb + (size_t)i * 128 + 4 * lane) = st;
}

// ------- layer1 GEMM: g_ha = relu(g_b1h[n,64] @ W + b)  (A fp16 exact, W split)
// CTA: 128x128; 8 warps = 4(m) x 2(n); warp tile 32x64. 2 MMAs/frag pair.
__global__ void __launch_bounds__(256)
k_gemm1(const float* __restrict__ W, const float* __restrict__ bias, int n) {
    __shared__ uint32_t Xs[128 * 17];
    __shared__ uint32_t WsHi[128 * 17], WsLo[128 * 17];
    const int K = 64;

    int tid = threadIdx.x, lane = tid & 31, warp = tid >> 5;
    int g = lane >> 2, t = lane & 3;
    int warp_m = warp & 3, warp_n = warp >> 2;
    int rb = blockIdx.x * 128;

    float c[2][8][4];
#pragma unroll
    for (int mi = 0; mi < 2; mi++)
#pragma unroll
        for (int nb = 0; nb < 8; nb++)
#pragma unroll
            for (int q = 0; q < 4; q++) c[mi][nb][q] = 0.f;

    for (int ch = 0; ch < 2; ch++) {
        int c0 = ch * 32;
        __syncthreads();
        for (int idx = tid; idx < 128 * 16; idx += 256) {
            int r = idx >> 4, kk = idx & 15;
            int row = rb + r;
            uint32_t v = 0;
            if (row < n) v = ((const uint32_t*)(g_b1h + (size_t)row * K))[c0 / 2 + kk];
            Xs[r * 17 + kk] = v;
        }
        for (int idx = tid; idx < 128 * 16; idx += 256) {
            int kk = idx >> 7, nn = idx & 127;
            float2 v;
            v.x = W[(size_t)(c0 + 2 * kk) * 128 + nn];
            v.y = W[(size_t)(c0 + 2 * kk + 1) * 128 + nn];
            uint32_t hi, lo;
            split2h(v, hi, lo);
            WsHi[nn * 17 + kk] = hi;
            WsLo[nn * 17 + kk] = lo;
        }
        __syncthreads();

#pragma unroll
        for (int step = 0; step < 2; step++) {
            int kb = step * 8;
            uint32_t bh0[8], bh1[8], bl0[8], bl1[8];
#pragma unroll
            for (int nb = 0; nb < 8; nb++) {
                int nl = warp_n * 64 + nb * 8 + g;
                bh0[nb] = WsHi[nl * 17 + kb + t];
                bh1[nb] = WsHi[nl * 17 + kb + t + 4];
                bl0[nb] = WsLo[nl * 17 + kb + t];
                bl1[nb] = WsLo[nl * 17 + kb + t + 4];
            }
#pragma unroll
            for (int mi = 0; mi < 2; mi++) {
                int rl = warp_m * 32 + mi * 16 + g;
                uint32_t a0 = Xs[rl * 17 + kb + t];
                uint32_t a1 = Xs[(rl + 8) * 17 + kb + t];
                uint32_t a2 = Xs[rl * 17 + kb + t + 4];
                uint32_t a3 = Xs[(rl + 8) * 17 + kb + t + 4];
#pragma unroll
                for (int nb = 0; nb < 8; nb++) {
                    mma_f16(c[mi][nb][0], c[mi][nb][1], c[mi][nb][2], c[mi][nb][3],
                            a0, a1, a2, a3, bh0[nb], bh1[nb]);
                    mma_f16(c[mi][nb][0], c[mi][nb][1], c[mi][nb][2], c[mi][nb][3],
                            a0, a1, a2, a3, bl0[nb], bl1[nb]);
                }
            }
        }
    }

#pragma unroll
    for (int mi = 0; mi < 2; mi++) {
        int row0 = rb + warp_m * 32 + mi * 16 + g;
        int row1 = row0 + 8;
#pragma unroll
        for (int nb = 0; nb < 8; nb++) {
            int col = warp_n * 64 + nb * 8 + 2 * t;
            float b0 = bias[col], b1 = bias[col + 1];
            if (row0 < n) {
                __half2 h = __floats2half2_rn(fmaxf(c[mi][nb][0] + b0, 0.f),
                                              fmaxf(c[mi][nb][1] + b1, 0.f));
                *(__half2*)(g_ha + (size_t)row0 * 128 + col) = h;
            }
            if (row1 < n) {
                __half2 h = __floats2half2_rn(fmaxf(c[mi][nb][2] + b0, 0.f),
                                              fmaxf(c[mi][nb][3] + b1, 0.f));
                *(__half2*)(g_ha + (size_t)row1 * 128 + col) = h;
            }
        }
    }
}

// ------- layer2 GEMM + bias + relu + head + log_softmax (fused, 128-tile) ----
// A from g_hb (fp16, exact). Dynamic smem:
//   [0,8704)        Xs       (128*17 u32)      \
//   [8704,17408)    WsHi                        | aliased by H2 [0,67584)
//   [17408,26112)   WsLo                       /
//   [67584,72704)   Wt (10x128 f32 transposed)
//   [72704,72744)   bls
#define SM2_TOTAL 72768
__global__ void __launch_bounds__(256)
k_gemm2_head(const float* __restrict__ W, const float* __restrict__ bias,
             const float* __restrict__ Wl, const float* __restrict__ bl,
             float* __restrict__ out, int n) {
    extern __shared__ __align__(16) char sm[];
    uint32_t* Xs   = (uint32_t*)(sm);
    uint32_t* WsHi = (uint32_t*)(sm + 8704);
    uint32_t* WsLo = (uint32_t*)(sm + 17408);
    float*    H2   = (float*)(sm);
    float*    Wt   = (float*)(sm + 67584);
    float*    bls  = (float*)(sm + 72704);

    const int K = 128;
    int tid = threadIdx.x, lane = tid & 31, warp = tid >> 5;
    int g = lane >> 2, t = lane & 3;
    int warp_m = warp & 3, warp_n = warp >> 2;
    int rb = blockIdx.x * 128;

    for (int idx = tid; idx < 1280; idx += 256) {
        int k = idx / 10, j = idx - 10 * k;
        Wt[j * 128 + k] = Wl[idx];
    }
    if (tid < 10) bls[tid] = bl[tid];

    float c[2][8][4];
#pragma unroll
    for (int mi = 0; mi < 2; mi++)
#pragma unroll
        for (int nb = 0; nb < 8; nb++)
#pragma unroll
            for (int q = 0; q < 4; q++) c[mi][nb][q] = 0.f;

    for (int ch = 0; ch < 4; ch++) {
        int c0 = ch * 32;
        __syncthreads();
        for (int idx = tid; idx < 128 * 16; idx += 256) {
            int r = idx >> 4, kk = idx & 15;
            int row = rb + r;
            uint32_t v = 0;
            if (row < n) v = ((const uint32_t*)(g_hb + (size_t)row * K))[c0 / 2 + kk];
            Xs[r * 17 + kk] = v;
        }
        for (int idx = tid; idx < 128 * 16; idx += 256) {
            int kk = idx >> 7, nn = idx & 127;
            float2 v;
            v.x = W[(size_t)(c0 + 2 * kk) * 128 + nn];
            v.y = W[(size_t)(c0 + 2 * kk + 1) * 128 + nn];
            uint32_t hi, lo;
            split2h(v, hi, lo);
            WsHi[nn * 17 + kk] = hi;
            WsLo[nn * 17 + kk] = lo;
        }
        __syncthreads();

#pragma unroll
        for (int step = 0; step < 2; step++) {
            int kb = step * 8;
            uint32_t bh0[8], bh1[8], bl0[8], bl1[8];
#pragma unroll
            for (int nb = 0; nb < 8; nb++) {
                int nl = warp_n * 64 + nb * 8 + g;
                bh0[nb] = WsHi[nl * 17 + kb + t];
                bh1[nb] = WsHi[nl * 17 + kb + t + 4];
                bl0[nb] = WsLo[nl * 17 + kb + t];
                bl1[nb] = WsLo[nl * 17 + kb + t + 4];
            }
#pragma unroll
            for (int mi = 0; mi < 2; mi++) {
                int rl = warp_m * 32 + mi * 16 + g;
                uint32_t a0 = Xs[rl * 17 + kb + t];
                uint32_t a1 = Xs[(rl + 8) * 17 + kb + t];
                uint32_t a2 = Xs[rl * 17 + kb + t + 4];
                uint32_t a3 = Xs[(rl + 8) * 17 + kb + t + 4];
#pragma unroll
                for (int nb = 0; nb < 8; nb++) {
                    mma_f16(c[mi][nb][0], c[mi][nb][1], c[mi][nb][2], c[mi][nb][3],
                            a0, a1, a2, a3, bh0[nb], bh1[nb]);
                    mma_f16(c[mi][nb][0], c[mi][nb][1], c[mi][nb][2], c[mi][nb][3],
                            a0, a1, a2, a3, bl0[nb], bl1[nb]);
                }
            }
        }
    }

    // epilogue: bias + relu into smem H2 (stride 132, conflict-free)
    __syncthreads();
#pragma unroll
    for (int mi = 0; mi < 2; mi++) {
        int r0 = warp_m * 32 + mi * 16 + g;
        int r1 = r0 + 8;
#pragma unroll
        for (int nb = 0; nb < 8; nb++) {
            int col = warp_n * 64 + nb * 8 + 2 * t;
            float b0 = bias[col], b1 = bias[col + 1];
            H2[r0 * 132 + col]     = fmaxf(c[mi][nb][0] + b0, 0.f);
            H2[r0 * 132 + col + 1] = fmaxf(c[mi][nb][1] + b1, 0.f);
            H2[r1 * 132 + col]     = fmaxf(c[mi][nb][2] + b0, 0.f);
            H2[r1 * 132 + col + 1] = fmaxf(c[mi][nb][3] + b1, 0.f);
        }
    }
    __syncthreads();

    // head: each warp handles 16 rows; log_softmax; write out only
    for (int it = 0; it < 16; it++) {
        int r = warp * 16 + it;
        int i = rb + r;
        if (i >= n) break;
        float4 hv = *(const float4*)(H2 + r * 132 + 4 * lane);
        float lg[10];
#pragma unroll
        for (int j = 0; j < 10; j++) {
            float4 wv = ((const float4*)(Wt + j * 128))[lane];
            float p = hv.x * wv.x + hv.y * wv.y + hv.z * wv.z + hv.w * wv.w;
#pragma unroll
            for (int o = 16; o; o >>= 1) p += __shfl_xor_sync(0xffffffffu, p, o);
            lg[j] = p + bls[j];
        }
        float m = lg[0];
#pragma unroll
        for (int j = 1; j < 10; j++) m = fmaxf(m, lg[j]);
        float s = 0.f;
#pragma unroll
        for (int j = 0; j < 10; j++) s += expf(lg[j] - m);
        float lse = m + logf(s);
        if (lane < 10) out[(size_t)i * 10 + lane] = lg[lane] - lse;
    }
}

// ---------------- launch -----------------------------------------------------
extern "C" void kernel_launch(void* const* d_in, const int* in_sizes, int n_in,
                              void* d_out, int out_size) {
    const float* x  = (const float*)d_in[0];
    const void*  ei = d_in[1];
    const float* W1 = (const float*)d_in[2];
    const float* b1 = (const float*)d_in[3];
    const float* W2 = (const float*)d_in[4];
    const float* b2 = (const float*)d_in[5];
    const float* Wl = (const float*)d_in[6];
    const float* bl = (const float*)d_in[7];
    float* out = (float*)d_out;

    int N = in_sizes[0] / 64;
    int E = in_sizes[1] / 2;

    static bool attr_done = false;
    if (!attr_done) {
        cudaFuncSetAttribute(k_gemm2_head, cudaFuncAttributeMaxDynamicSharedMemorySize, SM2_TOTAL);
        attr_done = true;
    }

    // --- CSR build ---
    k_zero_detect<<<ceil_div(N, 256), 256>>>((const int*)ei, 2 * E >= 2048 ? 2048 : 2 * E, N);
    k_hist<<<ceil_div(E, 256), 256>>>(ei, E, N);
    k_scan1<<<ceil_div(N, 2048), 256>>>(N);
    k_scan3<<<ceil_div(N, 256), 256>>>(N, E);
    k_fill<<<ceil_div(E, 256), 256>>>(ei, E, N);

    // --- layer 1 (agg-first): agg x -> g_b1h (fp16); gemm -> g_ha (fp16)
    k_agg1<<<ceil_div(N, 8), 256>>>(x, N);
    k_gemm1<<<ceil_div(N, 128), 256>>>(W1, b1, N);

    // --- layer 2: agg g_ha -> g_hb (fp16); fused gemm+head -> out
    k_agg2<<<ceil_div(N, 8), 256>>>(N);
    k_gemm2_head<<<ceil_div(N, 128), 256, SM2_TOTAL>>>(W2, b2, Wl, bl, out, N);
}

// round 17
// speedup vs baseline: 1.1799x; 1.0185x over previous
#include <cuda_runtime.h>
#include <cuda_bf16.h>
#include <cuda_fp16.h>
#include <math.h>
#include <cstdint>

#define NMAX 100000
#define EMAX 1000000
#define HID 128

// ---------------- scratch (device globals; no runtime allocation) ------------
__device__ __align__(16) int    g_cnt[NMAX];
__device__ __align__(16) int    g_off[NMAX + 1];
__device__ __align__(16) int    g_cur[NMAX];
__device__ __align__(16) float  g_dinv[NMAX];
__device__ __align__(16) int2   g_edge[EMAX];              // {src, w bits}
__device__ __align__(16) __half g_xh[(size_t)NMAX * 64];   // x in fp16
__device__ __align__(16) __half g_b1h[(size_t)NMAX * 64];  // agg1 out (fp16)
__device__ __align__(16) __half g_ha[(size_t)NMAX * HID];  // H1 (fp16)
__device__ __align__(16) __half g_hb[(size_t)NMAX * HID];  // agg2 out (fp16)
__device__ __align__(16) int    g_bsums[64];
__device__ int g_is64;

static inline int ceil_div(int a, int b) { return (a + b - 1) / b; }

// ---------------- helpers ----------------------------------------------------
__device__ __forceinline__ int load_idx(const void* p, int is64, long long i) {
    if (is64) return (int)((const long long*)p)[i];
    return ((const int*)p)[i];
}

// split a float2 into packed fp16x2 hi and lo words (W path; err ~2^-22)
__device__ __forceinline__ void split2h(float2 v, uint32_t& hi, uint32_t& lo) {
    __half hx = __float2half_rn(v.x), hy = __float2half_rn(v.y);
    float rx = v.x - __half2float(hx);
    float ry = v.y - __half2float(hy);
    __half lx = __float2half_rn(rx), ly = __float2half_rn(ry);
    hi = ((uint32_t)__half_as_ushort(hy) << 16) | (uint32_t)__half_as_ushort(hx);
    lo = ((uint32_t)__half_as_ushort(ly) << 16) | (uint32_t)__half_as_ushort(lx);
}

__device__ __forceinline__ void mma_f16(float& c0, float& c1, float& c2, float& c3,
                                        uint32_t a0, uint32_t a1, uint32_t a2, uint32_t a3,
                                        uint32_t b0, uint32_t b1) {
    asm volatile(
        "mma.sync.aligned.m16n8k16.row.col.f32.f16.f16.f32 "
        "{%0,%1,%2,%3}, {%4,%5,%6,%7}, {%8,%9}, {%0,%1,%2,%3};"
        : "+f"(c0), "+f"(c1), "+f"(c2), "+f"(c3)
        : "r"(a0), "r"(a1), "r"(a2), "r"(a3), "r"(b0), "r"(b1));
}

// ---------------- zero counters + dtype detect (fused) ------------------------
__global__ void k_zero_detect(const int* __restrict__ p, int nwords, int n) {
    int i = blockIdx.x * blockDim.x + threadIdx.x;
    if (i < n) g_cnt[i] = 0;
    if (blockIdx.x == 0 && threadIdx.x < 32) {
        bool oddzero = true;
        for (int j = threadIdx.x; j < 1024; j += 32) {
            int w = 2 * j + 1;
            if (w < nwords && p[w] != 0) oddzero = false;
        }
        oddzero = __all_sync(0xffffffffu, oddzero);
        if (threadIdx.x == 0) g_is64 = oddzero ? 1 : 0;
    }
}

// ---------------- x -> fp16 conversion ----------------------------------------
__global__ void k_convx(const float* __restrict__ X, int total) {
    int i = blockIdx.x * blockDim.x + threadIdx.x;  // handles 4 floats
    int base = i * 4;
    if (base < total) {
        float4 v = *(const float4*)(X + base);
        uint2 st;
        *(__half2*)&st.x = __floats2half2_rn(v.x, v.y);
        *(__half2*)&st.y = __floats2half2_rn(v.z, v.w);
        *(uint2*)(g_xh + base) = st;
    }
}

__global__ void k_hist(const void* __restrict__ ei, int ne, int n) {
    int e = blockIdx.x * blockDim.x + threadIdx.x;
    int is64 = g_is64;
    if (e < ne) {
        int d = load_idx(ei, is64, (long long)ne + e);
        if (d >= 0 && d < n) atomicAdd(&g_cnt[d], 1);
    }
}

__global__ void k_scan1(int n) {
    __shared__ int sh[256];
    int tid  = threadIdx.x;
    int base = blockIdx.x * 2048;
    int vals[8];
    int tsum = 0;
#pragma unroll
    for (int v = 0; v < 8; v++) {
        int idx = base + tid * 8 + v;
        vals[v] = (idx < n) ? g_cnt[idx] : 0;
        tsum += vals[v];
    }
    sh[tid] = tsum;
    __syncthreads();
    for (int s = 1; s < 256; s <<= 1) {
        int t = (tid >= s) ? sh[tid - s] : 0;
        __syncthreads();
        sh[tid] += t;
        __syncthreads();
    }
    int run = sh[tid] - tsum;
    if (tid == 255) g_bsums[blockIdx.x] = sh[255];
#pragma unroll
    for (int v = 0; v < 8; v++) {
        int idx = base + tid * 8 + v;
        if (idx < n) g_off[idx] = run;
        run += vals[v];
    }
}

// scan3: parallel prefix over g_bsums (64 lanes + shfl reduce)
__global__ void k_scan3(int n, int ne) {
    __shared__ int wsum[2];
    int tid = threadIdx.x;
    int b = blockIdx.x;
    int grp = b >> 3;
    if (tid < 64) {
        int v = (tid < grp) ? g_bsums[tid] : 0;
#pragma unroll
        for (int o = 16; o; o >>= 1) v += __shfl_down_sync(0xffffffffu, v, o);
        if ((tid & 31) == 0) wsum[tid >> 5] = v;
    }
    __syncthreads();
    int pre = wsum[0] + wsum[1];
    int i = b * 256 + tid;
    if (i < n) {
        int o = g_off[i] + pre;
        g_off[i] = o;
        g_cur[i] = o;
        g_dinv[i] = rsqrtf((float)(g_cnt[i] + 1));  // +1 self loop
        if (i == 0) g_off[n] = ne;
    }
}

__global__ void k_fill(const void* __restrict__ ei, int ne, int n) {
    int e = blockIdx.x * blockDim.x + threadIdx.x;
    int is64 = g_is64;
    if (e < ne) {
        int s = load_idx(ei, is64, e);
        int d = load_idx(ei, is64, (long long)ne + e);
        if (s >= 0 && s < n && d >= 0 && d < n) {
            int p = atomicAdd(&g_cur[d], 1);
            g_edge[p] = make_int2(s, __float_as_int(g_dinv[s] * g_dinv[d]));
        }
    }
}

// ------- agg1 (fp16 in/out, 64-wide): g_b1h[i] = sum norm*xh[j] + dinv^2 xh[i]
__global__ void k_agg1(int n) {
    int lane = threadIdx.x & 31, warp = threadIdx.x >> 5;
    int i = blockIdx.x * 8 + warp;
    if (i >= n) return;
    int e0 = g_off[i], e1 = g_off[i + 1];
    float di = g_dinv[i];
    float sw = di * di;

    float2 a0 = make_float2(0.f, 0.f), a1 = make_float2(0.f, 0.f);
    int e = e0;
    for (; e + 1 < e1; e += 2) {
        int2 ea = g_edge[e], eb = g_edge[e + 1];
        float wa = __int_as_float(ea.y), wb = __int_as_float(eb.y);
        uint32_t ra = *(const uint32_t*)(g_xh + (size_t)ea.x * 64 + 2 * lane);
        uint32_t rb = *(const uint32_t*)(g_xh + (size_t)eb.x * 64 + 2 * lane);
        float2 fa = __half22float2(*(__half2*)&ra);
        float2 fb = __half22float2(*(__half2*)&rb);
        a0.x = fmaf(wa, fa.x, a0.x); a0.y = fmaf(wa, fa.y, a0.y);
        a1.x = fmaf(wb, fb.x, a1.x); a1.y = fmaf(wb, fb.y, a1.y);
    }
    if (e < e1) {
        int2 ea = g_edge[e];
        float wa = __int_as_float(ea.y);
        uint32_t ra = *(const uint32_t*)(g_xh + (size_t)ea.x * 64 + 2 * lane);
        float2 fa = __half22float2(*(__half2*)&ra);
        a0.x = fmaf(wa, fa.x, a0.x); a0.y = fmaf(wa, fa.y, a0.y);
    }
    uint32_t rs = *(const uint32_t*)(g_xh + (size_t)i * 64 + 2 * lane);
    float2 fs = __half22float2(*(__half2*)&rs);
    float ox = fmaf(sw, fs.x, a0.x + a1.x);
    float oy = fmaf(sw, fs.y, a0.y + a1.y);
    *(__half2*)(g_b1h + (size_t)i * 64 + 2 * lane) = __floats2half2_rn(ox, oy);
}

// ------- agg2 (fp16 in/out, 128-wide): g_hb[i] = sum norm*g_ha[j] + dinv^2 g_ha[i]
__global__ void k_agg2(int n) {
    int lane = threadIdx.x & 31, warp = threadIdx.x >> 5;
    int i = blockIdx.x * 8 + warp;
    if (i >= n) return;
    int e0 = g_off[i], e1 = g_off[i + 1];
    float di = g_dinv[i];
    float sw = di * di;

    float4 a0 = make_float4(0.f, 0.f, 0.f, 0.f), a1 = a0;
    int e = e0;
    for (; e + 1 < e1; e += 2) {
        int2 ea = g_edge[e], eb = g_edge[e + 1];
        float wa = __int_as_float(ea.y), wb = __int_as_float(eb.y);
        uint2 ra = *(const uint2*)(g_ha + (size_t)ea.x * 128 + 4 * lane);
        uint2 rb = *(const uint2*)(g_ha + (size_t)eb.x * 128 + 4 * lane);
        float2 fa0 = __half22float2(*(__half2*)&ra.x), fa1 = __half22float2(*(__half2*)&ra.y);
        float2 fb0 = __half22float2(*(__half2*)&rb.x), fb1 = __half22float2(*(__half2*)&rb.y);
        a0.x = fmaf(wa, fa0.x, a0.x); a0.y = fmaf(wa, fa0.y, a0.y);
        a0.z = fmaf(wa, fa1.x, a0.z); a0.w = fmaf(wa, fa1.y, a0.w);
        a1.x = fmaf(wb, fb0.x, a1.x); a1.y = fmaf(wb, fb0.y, a1.y);
        a1.z = fmaf(wb, fb1.x, a1.z); a1.w = fmaf(wb, fb1.y, a1.w);
    }
    if (e < e1) {
        int2 ea = g_edge[e];
        float wa = __int_as_float(ea.y);
        uint2 ra = *(const uint2*)(g_ha + (size_t)ea.x * 128 + 4 * lane);
        float2 fa0 = __half22float2(*(__half2*)&ra.x), fa1 = __half22float2(*(__half2*)&ra.y);
        a0.x = fmaf(wa, fa0.x, a0.x); a0.y = fmaf(wa, fa0.y, a0.y);
        a0.z = fmaf(wa, fa1.x, a0.z); a0.w = fmaf(wa, fa1.y, a0.w);
    }
    uint2 rs = *(const uint2*)(g_ha + (size_t)i * 128 + 4 * lane);
    float2 fs0 = __half22float2(*(__half2*)&rs.x), fs1 = __half22float2(*(__half2*)&rs.y);
    float ox = fmaf(sw, fs0.x, a0.x + a1.x);
    float oy = fmaf(sw, fs0.y, a0.y + a1.y);
    float oz = fmaf(sw, fs1.x, a0.z + a1.z);
    float ow = fmaf(sw, fs1.y, a0.w + a1.w);
    uint2 st;
    *(__half2*)&st.x = __floats2half2_rn(ox, oy);
    *(__half2*)&st.y = __floats2half2_rn(oz, ow);
    *(uint2*)(g_hb + (size_t)i * 128 + 4 * lane) = st;
}

// ------- layer1 GEMM: g_ha = relu(g_b1h[n,64] @ W + b)  (A fp16 exact, W split)
__global__ void __launch_bounds__(256)
k_gemm1(const float* __restrict__ W, const float* __restrict__ bias, int n) {
    __shared__ uint32_t Xs[128 * 17];
    __shared__ uint32_t WsHi[128 * 17], WsLo[128 * 17];
    const int K = 64;

    int tid = threadIdx.x, lane = tid & 31, warp = tid >> 5;
    int g = lane >> 2, t = lane & 3;
    int warp_m = warp & 3, warp_n = warp >> 2;
    int rb = blockIdx.x * 128;

    float c[2][8][4];
#pragma unroll
    for (int mi = 0; mi < 2; mi++)
#pragma unroll
        for (int nb = 0; nb < 8; nb++)
#pragma unroll
            for (int q = 0; q < 4; q++) c[mi][nb][q] = 0.f;

    for (int ch = 0; ch < 2; ch++) {
        int c0 = ch * 32;
        __syncthreads();
        for (int idx = tid; idx < 128 * 16; idx += 256) {
            int r = idx >> 4, kk = idx & 15;
            int row = rb + r;
            uint32_t v = 0;
            if (row < n) v = ((const uint32_t*)(g_b1h + (size_t)row * K))[c0 / 2 + kk];
            Xs[r * 17 + kk] = v;
        }
        for (int idx = tid; idx < 128 * 16; idx += 256) {
            int kk = idx >> 7, nn = idx & 127;
            float2 v;
            v.x = W[(size_t)(c0 + 2 * kk) * 128 + nn];
            v.y = W[(size_t)(c0 + 2 * kk + 1) * 128 + nn];
            uint32_t hi, lo;
            split2h(v, hi, lo);
            WsHi[nn * 17 + kk] = hi;
            WsLo[nn * 17 + kk] = lo;
        }
        __syncthreads();

#pragma unroll
        for (int step = 0; step < 2; step++) {
            int kb = step * 8;
            uint32_t bh0[8], bh1[8], bl0[8], bl1[8];
#pragma unroll
            for (int nb = 0; nb < 8; nb++) {
                int nl = warp_n * 64 + nb * 8 + g;
                bh0[nb] = WsHi[nl * 17 + kb + t];
                bh1[nb] = WsHi[nl * 17 + kb + t + 4];
                bl0[nb] = WsLo[nl * 17 + kb + t];
                bl1[nb] = WsLo[nl * 17 + kb + t + 4];
            }
#pragma unroll
            for (int mi = 0; mi < 2; mi++) {
                int rl = warp_m * 32 + mi * 16 + g;
                uint32_t a0 = Xs[rl * 17 + kb + t];
                uint32_t a1 = Xs[(rl + 8) * 17 + kb + t];
                uint32_t a2 = Xs[rl * 17 + kb + t + 4];
                uint32_t a3 = Xs[(rl + 8) * 17 + kb + t + 4];
#pragma unroll
                for (int nb = 0; nb < 8; nb++) {
                    mma_f16(c[mi][nb][0], c[mi][nb][1], c[mi][nb][2], c[mi][nb][3],
                            a0, a1, a2, a3, bh0[nb], bh1[nb]);
                    mma_f16(c[mi][nb][0], c[mi][nb][1], c[mi][nb][2], c[mi][nb][3],
                            a0, a1, a2, a3, bl0[nb], bl1[nb]);
                }
            }
        }
    }

#pragma unroll
    for (int mi = 0; mi < 2; mi++) {
        int row0 = rb + warp_m * 32 + mi * 16 + g;
        int row1 = row0 + 8;
#pragma unroll
        for (int nb = 0; nb < 8; nb++) {
            int col = warp_n * 64 + nb * 8 + 2 * t;
            float b0 = bias[col], b1 = bias[col + 1];
            if (row0 < n) {
                __half2 h = __floats2half2_rn(fmaxf(c[mi][nb][0] + b0, 0.f),
                                              fmaxf(c[mi][nb][1] + b1, 0.f));
                *(__half2*)(g_ha + (size_t)row0 * 128 + col) = h;
            }
            if (row1 < n) {
                __half2 h = __floats2half2_rn(fmaxf(c[mi][nb][2] + b0, 0.f),
                                              fmaxf(c[mi][nb][3] + b1, 0.f));
                *(__half2*)(g_ha + (size_t)row1 * 128 + col) = h;
            }
        }
    }
}

// ------- layer2 GEMM + bias + relu + head + log_softmax (fused, 128-tile) ----
#define SM2_TOTAL 72768
__global__ void __launch_bounds__(256)
k_gemm2_head(const float* __restrict__ W, const float* __restrict__ bias,
             const float* __restrict__ Wl, const float* __restrict__ bl,
             float* __restrict__ out, int n) {
    extern __shared__ __align__(16) char sm[];
    uint32_t* Xs   = (uint32_t*)(sm);
    uint32_t* WsHi = (uint32_t*)(sm + 8704);
    uint32_t* WsLo = (uint32_t*)(sm + 17408);
    float*    H2   = (float*)(sm);
    float*    Wt   = (float*)(sm + 67584);
    float*    bls  = (float*)(sm + 72704);

    const int K = 128;
    int tid = threadIdx.x, lane = tid & 31, warp = tid >> 5;
    int g = lane >> 2, t = lane & 3;
    int warp_m = warp & 3, warp_n = warp >> 2;
    int rb = blockIdx.x * 128;

    for (int idx = tid; idx < 1280; idx += 256) {
        int k = idx / 10, j = idx - 10 * k;
        Wt[j * 128 + k] = Wl[idx];
    }
    if (tid < 10) bls[tid] = bl[tid];

    float c[2][8][4];
#pragma unroll
    for (int mi = 0; mi < 2; mi++)
#pragma unroll
        for (int nb = 0; nb < 8; nb++)
#pragma unroll
            for (int q = 0; q < 4; q++) c[mi][nb][q] = 0.f;

    for (int ch = 0; ch < 4; ch++) {
        int c0 = ch * 32;
        __syncthreads();
        for (int idx = tid; idx < 128 * 16; idx += 256) {
            int r = idx >> 4, kk = idx & 15;
            int row = rb + r;
            uint32_t v = 0;
            if (row < n) v = ((const uint32_t*)(g_hb + (size_t)row * K))[c0 / 2 + kk];
            Xs[r * 17 + kk] = v;
        }
        for (int idx = tid; idx < 128 * 16; idx += 256) {
            int kk = idx >> 7, nn = idx & 127;
            float2 v;
            v.x = W[(size_t)(c0 + 2 * kk) * 128 + nn];
            v.y = W[(size_t)(c0 + 2 * kk + 1) * 128 + nn];
            uint32_t hi, lo;
            split2h(v, hi, lo);
            WsHi[nn * 17 + kk] = hi;
            WsLo[nn * 17 + kk] = lo;
        }
        __syncthreads();

#pragma unroll
        for (int step = 0; step < 2; step++) {
            int kb = step * 8;
            uint32_t bh0[8], bh1[8], bl0[8], bl1[8];
#pragma unroll
            for (int nb = 0; nb < 8; nb++) {
                int nl = warp_n * 64 + nb * 8 + g;
                bh0[nb] = WsHi[nl * 17 + kb + t];
                bh1[nb] = WsHi[nl * 17 + kb + t + 4];
                bl0[nb] = WsLo[nl * 17 + kb + t];
                bl1[nb] = WsLo[nl * 17 + kb + t + 4];
            }
#pragma unroll
            for (int mi = 0; mi < 2; mi++) {
                int rl = warp_m * 32 + mi * 16 + g;
                uint32_t a0 = Xs[rl * 17 + kb + t];
                uint32_t a1 = Xs[(rl + 8) * 17 + kb + t];
                uint32_t a2 = Xs[rl * 17 + kb + t + 4];
                uint32_t a3 = Xs[(rl + 8) * 17 + kb + t + 4];
#pragma unroll
                for (int nb = 0; nb < 8; nb++) {
                    mma_f16(c[mi][nb][0], c[mi][nb][1], c[mi][nb][2], c[mi][nb][3],
                            a0, a1, a2, a3, bh0[nb], bh1[nb]);
                    mma_f16(c[mi][nb][0], c[mi][nb][1], c[mi][nb][2], c[mi][nb][3],
                            a0, a1, a2, a3, bl0[nb], bl1[nb]);
                }
            }
        }
    }

    // epilogue: bias + relu into smem H2 (stride 132, conflict-free)
    __syncthreads();
#pragma unroll
    for (int mi = 0; mi < 2; mi++) {
        int r0 = warp_m * 32 + mi * 16 + g;
        int r1 = r0 + 8;
#pragma unroll
        for (int nb = 0; nb < 8; nb++) {
            int col = warp_n * 64 + nb * 8 + 2 * t;
            float b0 = bias[col], b1 = bias[col + 1];
            H2[r0 * 132 + col]     = fmaxf(c[mi][nb][0] + b0, 0.f);
            H2[r0 * 132 + col + 1] = fmaxf(c[mi][nb][1] + b1, 0.f);
            H2[r1 * 132 + col]     = fmaxf(c[mi][nb][2] + b0, 0.f);
            H2[r1 * 132 + col + 1] = fmaxf(c[mi][nb][3] + b1, 0.f);
        }
    }
    __syncthreads();

    // head: each warp handles 16 rows; log_softmax; write out only
    for (int it = 0; it < 16; it++) {
        int r = warp * 16 + it;
        int i = rb + r;
        if (i >= n) break;
        float4 hv = *(const float4*)(H2 + r * 132 + 4 * lane);
        float lg[10];
#pragma unroll
        for (int j = 0; j < 10; j++) {
            float4 wv = ((const float4*)(Wt + j * 128))[lane];
            float p = hv.x * wv.x + hv.y * wv.y + hv.z * wv.z + hv.w * wv.w;
#pragma unroll
            for (int o = 16; o; o >>= 1) p += __shfl_xor_sync(0xffffffffu, p, o);
            lg[j] = p + bls[j];
        }
        float m = lg[0];
#pragma unroll
        for (int j = 1; j < 10; j++) m = fmaxf(m, lg[j]);
        float s = 0.f;
#pragma unroll
        for (int j = 0; j < 10; j++) s += expf(lg[j] - m);
        float lse = m + logf(s);
        if (lane < 10) out[(size_t)i * 10 + lane] = lg[lane] - lse;
    }
}

// ---------------- launch -----------------------------------------------------
extern "C" void kernel_launch(void* const* d_in, const int* in_sizes, int n_in,
                              void* d_out, int out_size) {
    const float* x  = (const float*)d_in[0];
    const void*  ei = d_in[1];
    const float* W1 = (const float*)d_in[2];
    const float* b1 = (const float*)d_in[3];
    const float* W2 = (const float*)d_in[4];
    const float* b2 = (const float*)d_in[5];
    const float* Wl = (const float*)d_in[6];
    const float* bl = (const float*)d_in[7];
    float* out = (float*)d_out;

    int N = in_sizes[0] / 64;
    int E = in_sizes[1] / 2;

    static bool attr_done = false;
    if (!attr_done) {
        cudaFuncSetAttribute(k_gemm2_head, cudaFuncAttributeMaxDynamicSharedMemorySize, SM2_TOTAL);
        attr_done = true;
    }

    // --- CSR build + x conversion (independent; conversion overlaps) ---
    k_zero_detect<<<ceil_div(N, 256), 256>>>((const int*)ei, 2 * E >= 2048 ? 2048 : 2 * E, N);
    k_convx<<<ceil_div(N * 64 / 4, 256), 256>>>(x, N * 64);
    k_hist<<<ceil_div(E, 256), 256>>>(ei, E, N);
    k_scan1<<<ceil_div(N, 2048), 256>>>(N);
    k_scan3<<<ceil_div(N, 256), 256>>>(N, E);
    k_fill<<<ceil_div(E, 256), 256>>>(ei, E, N);

    // --- layer 1 (agg-first): agg xh (fp16) -> g_b1h; gemm -> g_ha (fp16)
    k_agg1<<<ceil_div(N, 8), 256>>>(N);
    k_gemm1<<<ceil_div(N, 128), 256>>>(W1, b1, N);

    // --- layer 2: agg g_ha -> g_hb (fp16); fused gemm+head -> out
    k_agg2<<<ceil_div(N, 8), 256>>>(N);
    k_gemm2_head<<<ceil_div(N, 128), 256, SM2_TOTAL>>>(W2, b2, Wl, bl, out, N);
}